// round 1
// baseline (speedup 1.0000x reference)
#include <cuda_runtime.h>
#include <math.h>

// ---------------- config ----------------
#define BATCH   16
#define SEQ     2048
#define NCH     64
#define DMODEL  256
#define DINNER  512
#define DSTATE  64
#define NHEADS  8
#define HP      64
#define CONVDIM 640          // DINNER + 2*DSTATE
#define DPROJ   1160         // 2*DINNER + 2*DSTATE + NHEADS
#define NROWS   (BATCH*SEQ)  // 32768
#define NLAYERS 4
#define LN_EPS  1e-5f

// ---------------- scratch (device globals; allocation-free) ----------------
__device__ float g_h[NROWS*DMODEL];      // residual stream
__device__ float g_zx[NROWS*DPROJ];      // zxbcdt = h @ W_in
__device__ float g_xact[NROWS*CONVDIM];  // silu(conv(xBC)+b)
__device__ float g_dt[NROWS*NHEADS];     // softplus(dt + bias)
__device__ float g_dA[NROWS*NHEADS];     // exp(dt * A)
__device__ float g_y[NROWS*DINNER];      // scan output, then gated+rmsnormed
__device__ float g_m[NROWS*DMODEL];      // y @ W_out

__device__ __forceinline__ float siluf(float x) {
    return x * (1.f / (1.f + __expf(-x)));
}

// ---------------- linear_in: h = x @ W + b  (K=64, N=256) ----------------
__global__ __launch_bounds__(DMODEL) void k_linear_in(
    const float* __restrict__ x, const float* __restrict__ w,
    const float* __restrict__ b)
{
    int row = blockIdx.x;
    int tid = threadIdx.x;
    __shared__ float xs[NCH];
    if (tid < NCH) xs[tid] = x[(size_t)row*NCH + tid];
    __syncthreads();
    float acc = b[tid];
#pragma unroll 8
    for (int k = 0; k < NCH; k++) acc += xs[k] * w[k*DMODEL + tid];
    g_h[(size_t)row*DMODEL + tid] = acc;
}

// ---------------- generic SGEMM: C[M,N] = A[M,K] @ B[K,N] ----------------
// 128x64 block tile, 16 k-slice, 8x4 per-thread microtile, 256 threads.
// M % 128 == 0, K % 16 == 0 assumed (true here); N guarded.
__global__ __launch_bounds__(256) void k_sgemm(
    const float* __restrict__ A, const float* __restrict__ Bm,
    float* __restrict__ C, int M, int N, int K)
{
    __shared__ float As[16][132];   // [k][m], padded
    __shared__ float Bs[16][64];    // [k][n]

    int tid = threadIdx.x;
    int m0 = blockIdx.y * 128;
    int n0 = blockIdx.x * 64;

    int arow = tid >> 1;            // 0..127
    int acol = (tid & 1) * 8;       // 0 or 8
    int brow = tid >> 4;            // 0..15
    int bcol = (tid & 15) * 4;      // 0..60
    int ty   = tid >> 4;            // 0..15 -> m sub-tile *8
    int tx   = tid & 15;            // 0..15 -> n sub-tile *4

    float acc[8][4];
#pragma unroll
    for (int i = 0; i < 8; i++)
#pragma unroll
        for (int j = 0; j < 4; j++) acc[i][j] = 0.f;

    const float* aptr = A + (size_t)(m0 + arow)*K + acol;

    for (int k0 = 0; k0 < K; k0 += 16) {
        float4 a0 = *(const float4*)(aptr + k0);
        float4 a1 = *(const float4*)(aptr + k0 + 4);
        As[acol+0][arow] = a0.x; As[acol+1][arow] = a0.y;
        As[acol+2][arow] = a0.z; As[acol+3][arow] = a0.w;
        As[acol+4][arow] = a1.x; As[acol+5][arow] = a1.y;
        As[acol+6][arow] = a1.z; As[acol+7][arow] = a1.w;

        int bn = n0 + bcol;
        float4 bv;
        if (bn + 3 < N) {
            bv = *(const float4*)(Bm + (size_t)(k0 + brow)*N + bn);
        } else {
            const float* bp = Bm + (size_t)(k0 + brow)*N;
            bv.x = (bn+0 < N) ? bp[bn+0] : 0.f;
            bv.y = (bn+1 < N) ? bp[bn+1] : 0.f;
            bv.z = (bn+2 < N) ? bp[bn+2] : 0.f;
            bv.w = (bn+3 < N) ? bp[bn+3] : 0.f;
        }
        *(float4*)(&Bs[brow][bcol]) = bv;
        __syncthreads();

#pragma unroll
        for (int kk = 0; kk < 16; kk++) {
            float4 t0 = *(const float4*)(&As[kk][ty*8]);
            float4 t1 = *(const float4*)(&As[kk][ty*8 + 4]);
            float4 tb = *(const float4*)(&Bs[kk][tx*4]);
            float ar[8] = {t0.x,t0.y,t0.z,t0.w,t1.x,t1.y,t1.z,t1.w};
            float br[4] = {tb.x,tb.y,tb.z,tb.w};
#pragma unroll
            for (int i = 0; i < 8; i++)
#pragma unroll
                for (int j = 0; j < 4; j++)
                    acc[i][j] += ar[i] * br[j];
        }
        __syncthreads();
    }

#pragma unroll
    for (int i = 0; i < 8; i++) {
        int m = m0 + ty*8 + i;
#pragma unroll
        for (int j = 0; j < 4; j++) {
            int n = n0 + tx*4 + j;
            if (n < N) C[(size_t)m*N + n] = acc[i][j];
        }
    }
}

// ------------- causal depthwise conv(4) + SiLU, plus dt/dA precompute -------------
__global__ __launch_bounds__(CONVDIM) void k_conv_dt(
    const float* __restrict__ conv_w, const float* __restrict__ conv_b,
    const float* __restrict__ dt_bias, const float* __restrict__ A_log,
    int layer)
{
    int t = blockIdx.x;
    int b = blockIdx.y;
    int c = threadIdx.x;                  // 0..639
    int rowbase = b*SEQ + t;

    const float* wr = conv_w + (size_t)layer*CONVDIM*4 + c*4;
    float s = conv_b[layer*CONVDIM + c];
    const float* zc = g_zx + (size_t)(b*SEQ)*DPROJ + DINNER + c;
#pragma unroll
    for (int j = 0; j < 4; j++) {
        int tt = t - 3 + j;
        if (tt >= 0) s += zc[(size_t)tt*DPROJ] * wr[j];
    }
    g_xact[(size_t)rowbase*CONVDIM + c] = siluf(s);

    if (c < NHEADS) {
        float draw = g_zx[(size_t)rowbase*DPROJ + DINNER + CONVDIM + c]
                     + dt_bias[layer*NHEADS + c];
        float dtv = (draw > 20.f) ? draw : log1pf(expf(draw));
        float Aneg = -expf(A_log[layer*NHEADS + c]);
        g_dt[rowbase*NHEADS + c] = dtv;
        g_dA[rowbase*NHEADS + c] = expf(dtv * Aneg);
    }
}

// ---------------- sequential selective scan ----------------
// grid = BATCH*NHEADS (128), block = 256: thread -> (p = tid/4, q = tid%4),
// each thread holds S[p, q*16 .. q*16+15] in registers for the whole sequence.
// No shared memory, no block syncs — only 2 shfls per step for the n-reduction.
__global__ __launch_bounds__(256) void k_scan(
    const float* __restrict__ Dp, int layer)
{
    int b = blockIdx.x >> 3;
    int h = blockIdx.x & 7;
    int tid = threadIdx.x;
    int p  = tid >> 2;
    int q  = tid & 3;
    int n0 = q * 16;

    float S[16];
#pragma unroll
    for (int j = 0; j < 16; j++) S[j] = 0.f;

    float Dh = Dp[layer*NHEADS + h];
    const float* rowp = g_xact + (size_t)(b*SEQ)*CONVDIM;
    const float* dtp  = g_dt  + (size_t)(b*SEQ)*NHEADS + h;
    const float* dAp  = g_dA  + (size_t)(b*SEQ)*NHEADS + h;
    float* yp = g_y + (size_t)(b*SEQ)*DINNER + h*HP + p;

    for (int t = 0; t < SEQ; t++) {
        const float* row = rowp + (size_t)t*CONVDIM;
        float xp  = row[h*HP + p];
        float dtv = dtp[t*NHEADS];
        float dAv = dAp[t*NHEADS];

        float Bf[16], Cf[16];
#pragma unroll
        for (int i = 0; i < 4; i++) {
            ((float4*)Bf)[i] = *(const float4*)(row + DINNER + n0 + i*4);
            ((float4*)Cf)[i] = *(const float4*)(row + DINNER + DSTATE + n0 + i*4);
        }

        float coef = dtv * xp;
        float acc = 0.f;
#pragma unroll
        for (int j = 0; j < 16; j++) {
            S[j] = S[j]*dAv + coef*Bf[j];
            acc += S[j]*Cf[j];
        }
        acc += __shfl_xor_sync(0xffffffffu, acc, 1);
        acc += __shfl_xor_sync(0xffffffffu, acc, 2);
        if (q == 0) yp[(size_t)t*DINNER] = acc + Dh*xp;
    }
}

// ---------------- gated RMSNorm: y = rmsnorm(y * silu(z)) * norm_w ----------------
__global__ __launch_bounds__(256) void k_gate_rms(
    const float* __restrict__ norm_w, int layer)
{
    int row = blockIdx.x;
    int tid = threadIdx.x;
    int lane = tid & 31, wid = tid >> 5;
    __shared__ float red[8];

    const float* zrow = g_zx + (size_t)row*DPROJ;
    float* yrow = g_y + (size_t)row*DINNER;

    float v0 = yrow[tid]       * siluf(zrow[tid]);
    float v1 = yrow[tid + 256] * siluf(zrow[tid + 256]);
    float s = v0*v0 + v1*v1;
#pragma unroll
    for (int o = 16; o > 0; o >>= 1) s += __shfl_xor_sync(0xffffffffu, s, o);
    if (lane == 0) red[wid] = s;
    __syncthreads();
    if (tid < 32) {
        float v = (lane < 8) ? red[lane] : 0.f;
#pragma unroll
        for (int o = 4; o > 0; o >>= 1) v += __shfl_xor_sync(0xffffffffu, v, o);
        if (lane == 0) red[0] = v;
    }
    __syncthreads();
    float scale = rsqrtf(red[0] * (1.f/DINNER) + LN_EPS);
    yrow[tid]       = v0 * scale * norm_w[layer*DINNER + tid];
    yrow[tid + 256] = v1 * scale * norm_w[layer*DINNER + tid + 256];
}

// ---------------- residual + LayerNorm: h = LN(m + h) ----------------
__global__ __launch_bounds__(256) void k_res_ln(
    const float* __restrict__ ln_w, const float* __restrict__ ln_b, int layer)
{
    int row = blockIdx.x;
    int tid = threadIdx.x;
    int lane = tid & 31, wid = tid >> 5;
    __shared__ float red1[8], red2[8];

    float u = g_m[(size_t)row*DMODEL + tid] + g_h[(size_t)row*DMODEL + tid];
    float s1 = u, s2 = u*u;
#pragma unroll
    for (int o = 16; o > 0; o >>= 1) {
        s1 += __shfl_xor_sync(0xffffffffu, s1, o);
        s2 += __shfl_xor_sync(0xffffffffu, s2, o);
    }
    if (lane == 0) { red1[wid] = s1; red2[wid] = s2; }
    __syncthreads();
    if (tid < 32) {
        float a = (lane < 8) ? red1[lane] : 0.f;
        float c = (lane < 8) ? red2[lane] : 0.f;
#pragma unroll
        for (int o = 4; o > 0; o >>= 1) {
            a += __shfl_xor_sync(0xffffffffu, a, o);
            c += __shfl_xor_sync(0xffffffffu, c, o);
        }
        if (lane == 0) { red1[0] = a; red2[0] = c; }
    }
    __syncthreads();
    float mu  = red1[0] * (1.f/DMODEL);
    float var = red2[0] * (1.f/DMODEL) - mu*mu;
    g_h[(size_t)row*DMODEL + tid] =
        (u - mu) * rsqrtf(var + LN_EPS) * ln_w[layer*DMODEL + tid]
        + ln_b[layer*DMODEL + tid];
}

// ---------------- linear_out: out = h @ W[256,5] + b ----------------
__global__ __launch_bounds__(160) void k_linear_out(
    const float* __restrict__ w, const float* __restrict__ bias,
    float* __restrict__ out)
{
    int row = blockIdx.x;
    int tid = threadIdx.x;
    int wid = tid >> 5;          // class 0..4
    int lane = tid & 31;
    const float* hr = g_h + (size_t)row*DMODEL;
    float acc = 0.f;
#pragma unroll
    for (int k = lane; k < DMODEL; k += 32) acc += hr[k] * w[k*5 + wid];
#pragma unroll
    for (int o = 16; o > 0; o >>= 1) acc += __shfl_xor_sync(0xffffffffu, acc, o);
    if (lane == 0) out[(size_t)row*5 + wid] = acc + bias[wid];
}

// ---------------- launcher ----------------
extern "C" void kernel_launch(void* const* d_in, const int* in_sizes, int n_in,
                              void* d_out, int out_size)
{
    const float* x         = (const float*)d_in[0];
    const float* lin_in_w  = (const float*)d_in[1];
    const float* lin_in_b  = (const float*)d_in[2];
    const float* W_in      = (const float*)d_in[3];
    const float* conv_w    = (const float*)d_in[4];
    const float* conv_b    = (const float*)d_in[5];
    const float* dt_bias   = (const float*)d_in[6];
    const float* A_log     = (const float*)d_in[7];
    const float* Dp        = (const float*)d_in[8];
    const float* norm_w    = (const float*)d_in[9];
    const float* W_out     = (const float*)d_in[10];
    const float* ln_w      = (const float*)d_in[11];
    const float* ln_b      = (const float*)d_in[12];
    const float* lin_out_w = (const float*)d_in[13];
    const float* lin_out_b = (const float*)d_in[14];
    float* out = (float*)d_out;

    void *ph, *pz, *py, *pm;
    cudaGetSymbolAddress(&ph, g_h);
    cudaGetSymbolAddress(&pz, g_zx);
    cudaGetSymbolAddress(&py, g_y);
    cudaGetSymbolAddress(&pm, g_m);

    k_linear_in<<<NROWS, DMODEL>>>(x, lin_in_w, lin_in_b);

    for (int l = 0; l < NLAYERS; l++) {
        // zxbcdt = h @ W_in[l]   (32768 x 1160 x 256)
        k_sgemm<<<dim3((DPROJ + 63)/64, NROWS/128), 256>>>(
            (const float*)ph, W_in + (size_t)l*DMODEL*DPROJ, (float*)pz,
            NROWS, DPROJ, DMODEL);

        k_conv_dt<<<dim3(SEQ, BATCH), CONVDIM>>>(conv_w, conv_b, dt_bias, A_log, l);

        k_scan<<<BATCH*NHEADS, 256>>>(Dp, l);

        k_gate_rms<<<NROWS, 256>>>(norm_w, l);

        // m = y @ W_out[l]       (32768 x 256 x 512)
        k_sgemm<<<dim3(DMODEL/64, NROWS/128), 256>>>(
            (const float*)py, W_out + (size_t)l*DINNER*DMODEL, (float*)pm,
            NROWS, DMODEL, DINNER);

        k_res_ln<<<NROWS, 256>>>(ln_w, ln_b, l);
    }

    k_linear_out<<<NROWS, 160>>>(lin_out_w, lin_out_b, out);
}

// round 3
// speedup vs baseline: 1.2919x; 1.2919x over previous
#include <cuda_runtime.h>
#include <cuda_bf16.h>
#include <cstdint>
#include <math.h>

// ---------------- config ----------------
#define BATCH   16
#define SEQ     2048
#define NCH     64
#define DMODEL  256
#define DINNER  512
#define DSTATE  64
#define NHEADS  8
#define HP      64
#define CONVDIM 640          // DINNER + 2*DSTATE
#define DPROJ   1160         // 2*DINNER + 2*DSTATE + NHEADS
#define NROWS   (BATCH*SEQ)  // 32768
#define NLAYERS 4
#define LN_EPS  1e-5f

// ---------------- scratch (device globals; allocation-free) ----------------
__device__ float g_h[NROWS*DMODEL];      // residual stream
__device__ float g_zx[NROWS*DPROJ];      // zxbcdt = h @ W_in
__device__ float g_xact[NROWS*CONVDIM];  // silu(conv(xBC)+b)
__device__ float g_dt[NROWS*NHEADS];     // softplus(dt + bias)
__device__ float g_dA[NROWS*NHEADS];     // exp(dt * A)
__device__ float g_y[NROWS*DINNER];      // scan output, then gated+rmsnormed
__device__ float g_m[NROWS*DMODEL];      // y @ W_out

__device__ __forceinline__ float siluf(float x) {
    return x * (1.f / (1.f + __expf(-x)));
}

__device__ __forceinline__ uint32_t smem_u32(const void* p) {
    uint32_t a;
    asm("{ .reg .u64 t; cvta.to.shared.u64 t, %1; cvt.u32.u64 %0, t; }"
        : "=r"(a) : "l"(p));
    return a;
}

__device__ __forceinline__ uint32_t pk2(float a, float b) {
    uint32_t lo = __bfloat16_as_ushort(__float2bfloat16_rn(a));
    uint32_t hi = __bfloat16_as_ushort(__float2bfloat16_rn(b));
    return lo | (hi << 16);
}

#define LDM_X4(r0, r1, r2, r3, addr) \
    asm volatile("ldmatrix.sync.aligned.m8n8.x4.shared.b16 {%0,%1,%2,%3}, [%4];" \
        : "=r"(r0), "=r"(r1), "=r"(r2), "=r"(r3) : "r"(addr))

#define MMA_BF16(c, a, b0v, b1v) \
    asm volatile("mma.sync.aligned.m16n8k16.row.col.f32.bf16.bf16.f32 " \
        "{%0,%1,%2,%3}, {%4,%5,%6,%7}, {%8,%9}, {%0,%1,%2,%3};" \
        : "+f"((c)[0]), "+f"((c)[1]), "+f"((c)[2]), "+f"((c)[3]) \
        : "r"((a)[0]), "r"((a)[1]), "r"((a)[2]), "r"((a)[3]), \
          "r"(b0v), "r"(b1v))

// ============================================================================
// Tensor-core (mma.sync) split-bf16 GEMM: C[M,N] = A[M,K] @ B[K,N] (+bias)
// A@B ~= Ah@Bh + Ah@Bl + Al@Bh, fp32 accumulate -> ~1.6e-5 rel err.
// CTA tile 128x128, BK=32, 8 warps (4m x 2n), warp tile 32x64.
// Requires M%128==0, K%32==0; N arbitrary (guarded).
// smem rows padded: 40 bf16 (80B) -> conflict-free ldmatrix.
// ============================================================================
#define GSTRIDE 40
#define GTILEB  (128*GSTRIDE*2)   // 10240 bytes per tile

__global__ __launch_bounds__(256) void k_gemm_mma(
    const float* __restrict__ A, const float* __restrict__ B,
    const float* __restrict__ bias, float* __restrict__ C, int N, int K)
{
    __shared__ __align__(128) __nv_bfloat16 sm[4][128*GSTRIDE]; // Ah, Al, Bh, Bl

    int tid = threadIdx.x;
    int wid = tid >> 5, lane = tid & 31;
    int m0 = blockIdx.y * 128, n0 = blockIdx.x * 128;
    int wm = wid & 3, wn = wid >> 2;     // 4 x 2 warp grid

    float acc[2][8][4];
#pragma unroll
    for (int mt = 0; mt < 2; mt++)
#pragma unroll
        for (int nt = 0; nt < 8; nt++)
#pragma unroll
            for (int j = 0; j < 4; j++) acc[mt][nt][j] = 0.f;

    // loader indices
    const int ar = tid >> 1, ac = (tid & 1) * 16;     // A: row, col-group
    const int bn = tid & 127, bkh = (tid >> 7) * 16;  // B: n, k-half
    const int ngl = n0 + bn;
    const bool bvalid = (ngl < N);

    const uint32_t smb = smem_u32(sm);
    // ldmatrix per-lane byte offsets within a tile
    const uint32_t aoff = (uint32_t)((wm*32 + (lane & 7) + ((lane >> 3) & 1) * 8) * (GSTRIDE*2))
                        + ((lane >> 4) & 1) * 16;
    const uint32_t boff = (uint32_t)((wn*64 + (lane & 7) + ((lane >> 4) & 1) * 8) * (GSTRIDE*2))
                        + ((lane >> 3) & 1) * 16;

    const int NC = K >> 5;
    for (int c = 0; c < NC; c++) {
        // ---- A tile [128 x 32] fp32 -> hi/lo bf16 ----
        const float* ap = A + (size_t)(m0 + ar) * K + c * 32 + ac;
#pragma unroll
        for (int i = 0; i < 4; i++) {
            float4 v = *(const float4*)(ap + 4 * i);
            float hx = __bfloat162float(__float2bfloat16_rn(v.x));
            float hy = __bfloat162float(__float2bfloat16_rn(v.y));
            float hz = __bfloat162float(__float2bfloat16_rn(v.z));
            float hw = __bfloat162float(__float2bfloat16_rn(v.w));
            int e = ar * GSTRIDE + ac + 4 * i;
            *(uint2*)&sm[0][e] = make_uint2(pk2(v.x, v.y), pk2(v.z, v.w));
            *(uint2*)&sm[1][e] = make_uint2(pk2(v.x - hx, v.y - hy),
                                            pk2(v.z - hz, v.w - hw));
        }
        // ---- B tile: sm[2/3][n][k] = B[k][n], hi/lo ----
        {
            float xv[16];
#pragma unroll
            for (int j = 0; j < 16; j++)
                xv[j] = bvalid ? B[(size_t)(c * 32 + bkh + j) * N + ngl] : 0.f;
#pragma unroll
            for (int u = 0; u < 4; u++) {
                float x0 = xv[4*u+0], x1 = xv[4*u+1], x2 = xv[4*u+2], x3 = xv[4*u+3];
                float h0 = __bfloat162float(__float2bfloat16_rn(x0));
                float h1 = __bfloat162float(__float2bfloat16_rn(x1));
                float h2 = __bfloat162float(__float2bfloat16_rn(x2));
                float h3 = __bfloat162float(__float2bfloat16_rn(x3));
                int e = bn * GSTRIDE + bkh + 4 * u;
                *(uint2*)&sm[2][e] = make_uint2(pk2(x0, x1), pk2(x2, x3));
                *(uint2*)&sm[3][e] = make_uint2(pk2(x0 - h0, x1 - h1),
                                                pk2(x2 - h2, x3 - h3));
            }
        }
        __syncthreads();

        // ---- 3 passes: (Ah,Bh), (Ah,Bl), (Al,Bh) ----
#pragma unroll
        for (int pass = 0; pass < 3; pass++) {
            uint32_t abase = smb + (pass == 2 ? GTILEB : 0) + aoff;
            uint32_t bbase = smb + 2 * GTILEB + (pass == 1 ? GTILEB : 0) + boff;
#pragma unroll
            for (int ks = 0; ks < 2; ks++) {
                uint32_t ra[2][4];
                LDM_X4(ra[0][0], ra[0][1], ra[0][2], ra[0][3], abase + ks * 32);
                LDM_X4(ra[1][0], ra[1][1], ra[1][2], ra[1][3],
                       abase + ks * 32 + 16 * (GSTRIDE*2));
                uint32_t rb[8][2];
#pragma unroll
                for (int g = 0; g < 4; g++) {
                    LDM_X4(rb[2*g][0], rb[2*g][1], rb[2*g+1][0], rb[2*g+1][1],
                           bbase + ks * 32 + g * 16 * (GSTRIDE*2));
                }
#pragma unroll
                for (int mt = 0; mt < 2; mt++)
#pragma unroll
                    for (int nt = 0; nt < 8; nt++)
                        MMA_BF16(acc[mt][nt], ra[mt], rb[nt][0], rb[nt][1]);
            }
        }
        __syncthreads();
    }

    // ---- epilogue ----
    const int gid = lane >> 2, tig = lane & 3;
#pragma unroll
    for (int mt = 0; mt < 2; mt++) {
#pragma unroll
        for (int nt = 0; nt < 8; nt++) {
            int col = n0 + wn * 64 + nt * 8 + tig * 2;
            if (col < N) {
                int r0 = m0 + wm * 32 + mt * 16 + gid;
                float2 v0 = make_float2(acc[mt][nt][0], acc[mt][nt][1]);
                float2 v1 = make_float2(acc[mt][nt][2], acc[mt][nt][3]);
                if (bias) {
                    float b0 = bias[col], b1 = bias[col + 1];
                    v0.x += b0; v0.y += b1; v1.x += b0; v1.y += b1;
                }
                *(float2*)(C + (size_t)r0 * N + col) = v0;
                *(float2*)(C + (size_t)(r0 + 8) * N + col) = v1;
            }
        }
    }
}

// ------------- causal depthwise conv(4) + SiLU, plus dt/dA precompute -------------
__global__ __launch_bounds__(CONVDIM) void k_conv_dt(
    const float* __restrict__ conv_w, const float* __restrict__ conv_b,
    const float* __restrict__ dt_bias, const float* __restrict__ A_log,
    int layer)
{
    int t = blockIdx.x;
    int b = blockIdx.y;
    int c = threadIdx.x;                  // 0..639
    int rowbase = b*SEQ + t;

    const float* wr = conv_w + (size_t)layer*CONVDIM*4 + c*4;
    float s = conv_b[layer*CONVDIM + c];
    const float* zc = g_zx + (size_t)(b*SEQ)*DPROJ + DINNER + c;
#pragma unroll
    for (int j = 0; j < 4; j++) {
        int tt = t - 3 + j;
        if (tt >= 0) s += zc[(size_t)tt*DPROJ] * wr[j];
    }
    g_xact[(size_t)rowbase*CONVDIM + c] = siluf(s);

    if (c < NHEADS) {
        float draw = g_zx[(size_t)rowbase*DPROJ + DINNER + CONVDIM + c]
                     + dt_bias[layer*NHEADS + c];
        float dtv = (draw > 20.f) ? draw : log1pf(expf(draw));
        float Aneg = -expf(A_log[layer*NHEADS + c]);
        g_dt[rowbase*NHEADS + c] = dtv;
        g_dA[rowbase*NHEADS + c] = expf(dtv * Aneg);
    }
}

// ---------------- sequential selective scan (register prefetch) ----------------
__global__ __launch_bounds__(256) void k_scan(
    const float* __restrict__ Dp, int layer)
{
    int b = blockIdx.x >> 3;
    int h = blockIdx.x & 7;
    int tid = threadIdx.x;
    int p  = tid >> 2;
    int q  = tid & 3;
    int n0 = q * 16;

    float S[16];
#pragma unroll
    for (int j = 0; j < 16; j++) S[j] = 0.f;

    float Dh = Dp[layer*NHEADS + h];
    const float* rowp = g_xact + (size_t)(b*SEQ)*CONVDIM;
    const float* dtp  = g_dt  + (size_t)(b*SEQ)*NHEADS + h;
    const float* dAp  = g_dA  + (size_t)(b*SEQ)*NHEADS + h;
    float* yp = g_y + (size_t)(b*SEQ)*DINNER + h*HP + p;

    // prime t=0
    float xp  = rowp[h*HP + p];
    float dtv = dtp[0];
    float dAv = dAp[0];
    float Bf[16], Cf[16];
#pragma unroll
    for (int i = 0; i < 4; i++) {
        ((float4*)Bf)[i] = *(const float4*)(rowp + DINNER + n0 + i*4);
        ((float4*)Cf)[i] = *(const float4*)(rowp + DINNER + DSTATE + n0 + i*4);
    }

    for (int t = 0; t < SEQ; t++) {
        // prefetch t+1
        float xp2 = 0.f, dt2 = 0.f, dA2 = 0.f;
        float Bn[16], Cn[16];
        if (t + 1 < SEQ) {
            const float* r2 = rowp + (size_t)(t+1)*CONVDIM;
            xp2 = r2[h*HP + p];
            dt2 = dtp[(t+1)*NHEADS];
            dA2 = dAp[(t+1)*NHEADS];
#pragma unroll
            for (int i = 0; i < 4; i++) {
                ((float4*)Bn)[i] = *(const float4*)(r2 + DINNER + n0 + i*4);
                ((float4*)Cn)[i] = *(const float4*)(r2 + DINNER + DSTATE + n0 + i*4);
            }
        }

        float coef = dtv * xp;
        float acc = 0.f;
#pragma unroll
        for (int j = 0; j < 16; j++) {
            S[j] = S[j]*dAv + coef*Bf[j];
            acc += S[j]*Cf[j];
        }
        acc += __shfl_xor_sync(0xffffffffu, acc, 1);
        acc += __shfl_xor_sync(0xffffffffu, acc, 2);
        if (q == 0) yp[(size_t)t*DINNER] = acc + Dh*xp;

        xp = xp2; dtv = dt2; dAv = dA2;
#pragma unroll
        for (int j = 0; j < 16; j++) { Bf[j] = Bn[j]; Cf[j] = Cn[j]; }
    }
}

// ---------------- gated RMSNorm: y = rmsnorm(y * silu(z)) * norm_w ----------------
__global__ __launch_bounds__(256) void k_gate_rms(
    const float* __restrict__ norm_w, int layer)
{
    int row = blockIdx.x;
    int tid = threadIdx.x;
    int lane = tid & 31, wid = tid >> 5;
    __shared__ float red[8];

    const float* zrow = g_zx + (size_t)row*DPROJ;
    float* yrow = g_y + (size_t)row*DINNER;

    float v0 = yrow[tid]       * siluf(zrow[tid]);
    float v1 = yrow[tid + 256] * siluf(zrow[tid + 256]);
    float s = v0*v0 + v1*v1;
#pragma unroll
    for (int o = 16; o > 0; o >>= 1) s += __shfl_xor_sync(0xffffffffu, s, o);
    if (lane == 0) red[wid] = s;
    __syncthreads();
    if (tid < 32) {
        float v = (lane < 8) ? red[lane] : 0.f;
#pragma unroll
        for (int o = 4; o > 0; o >>= 1) v += __shfl_xor_sync(0xffffffffu, v, o);
        if (lane == 0) red[0] = v;
    }
    __syncthreads();
    float scale = rsqrtf(red[0] * (1.f/DINNER) + LN_EPS);
    yrow[tid]       = v0 * scale * norm_w[layer*DINNER + tid];
    yrow[tid + 256] = v1 * scale * norm_w[layer*DINNER + tid + 256];
}

// ---------------- residual + LayerNorm: h = LN(m + h) ----------------
__global__ __launch_bounds__(256) void k_res_ln(
    const float* __restrict__ ln_w, const float* __restrict__ ln_b, int layer)
{
    int row = blockIdx.x;
    int tid = threadIdx.x;
    int lane = tid & 31, wid = tid >> 5;
    __shared__ float red1[8], red2[8];

    float u = g_m[(size_t)row*DMODEL + tid] + g_h[(size_t)row*DMODEL + tid];
    float s1 = u, s2 = u*u;
#pragma unroll
    for (int o = 16; o > 0; o >>= 1) {
        s1 += __shfl_xor_sync(0xffffffffu, s1, o);
        s2 += __shfl_xor_sync(0xffffffffu, s2, o);
    }
    if (lane == 0) { red1[wid] = s1; red2[wid] = s2; }
    __syncthreads();
    if (tid < 32) {
        float a = (lane < 8) ? red1[lane] : 0.f;
        float c = (lane < 8) ? red2[lane] : 0.f;
#pragma unroll
        for (int o = 4; o > 0; o >>= 1) {
            a += __shfl_xor_sync(0xffffffffu, a, o);
            c += __shfl_xor_sync(0xffffffffu, c, o);
        }
        if (lane == 0) { red1[0] = a; red2[0] = c; }
    }
    __syncthreads();
    float mu  = red1[0] * (1.f/DMODEL);
    float var = red2[0] * (1.f/DMODEL) - mu*mu;
    g_h[(size_t)row*DMODEL + tid] =
        (u - mu) * rsqrtf(var + LN_EPS) * ln_w[layer*DMODEL + tid]
        + ln_b[layer*DMODEL + tid];
}

// ---------------- linear_out: out = h @ W[256,5] + b ----------------
__global__ __launch_bounds__(160) void k_linear_out(
    const float* __restrict__ w, const float* __restrict__ bias,
    float* __restrict__ out)
{
    int row = blockIdx.x;
    int tid = threadIdx.x;
    int wid = tid >> 5;          // class 0..4
    int lane = tid & 31;
    const float* hr = g_h + (size_t)row*DMODEL;
    float acc = 0.f;
#pragma unroll
    for (int k = lane; k < DMODEL; k += 32) acc += hr[k] * w[k*5 + wid];
#pragma unroll
    for (int o = 16; o > 0; o >>= 1) acc += __shfl_xor_sync(0xffffffffu, acc, o);
    if (lane == 0) out[(size_t)row*5 + wid] = acc + bias[wid];
}

// ---------------- launcher ----------------
extern "C" void kernel_launch(void* const* d_in, const int* in_sizes, int n_in,
                              void* d_out, int out_size)
{
    const float* x         = (const float*)d_in[0];
    const float* lin_in_w  = (const float*)d_in[1];
    const float* lin_in_b  = (const float*)d_in[2];
    const float* W_in      = (const float*)d_in[3];
    const float* conv_w    = (const float*)d_in[4];
    const float* conv_b    = (const float*)d_in[5];
    const float* dt_bias   = (const float*)d_in[6];
    const float* A_log     = (const float*)d_in[7];
    const float* Dp        = (const float*)d_in[8];
    const float* norm_w    = (const float*)d_in[9];
    const float* W_out     = (const float*)d_in[10];
    const float* ln_w      = (const float*)d_in[11];
    const float* ln_b      = (const float*)d_in[12];
    const float* lin_out_w = (const float*)d_in[13];
    const float* lin_out_b = (const float*)d_in[14];
    float* out = (float*)d_out;

    void *ph, *pz, *py, *pm;
    cudaGetSymbolAddress(&ph, g_h);
    cudaGetSymbolAddress(&pz, g_zx);
    cudaGetSymbolAddress(&py, g_y);
    cudaGetSymbolAddress(&pm, g_m);

    // linear_in: h = x @ lin_in_w + b   (32768 x 256 x 64)
    k_gemm_mma<<<dim3(2, NROWS/128), 256>>>(x, lin_in_w, lin_in_b,
                                            (float*)ph, DMODEL, NCH);

    for (int l = 0; l < NLAYERS; l++) {
        // zxbcdt = h @ W_in[l]   (32768 x 1160 x 256)
        k_gemm_mma<<<dim3((DPROJ + 127)/128, NROWS/128), 256>>>(
            (const float*)ph, W_in + (size_t)l*DMODEL*DPROJ, nullptr,
            (float*)pz, DPROJ, DMODEL);

        k_conv_dt<<<dim3(SEQ, BATCH), CONVDIM>>>(conv_w, conv_b, dt_bias, A_log, l);

        k_scan<<<BATCH*NHEADS, 256>>>(Dp, l);

        k_gate_rms<<<NROWS, 256>>>(norm_w, l);

        // m = y @ W_out[l]       (32768 x 256 x 512)
        k_gemm_mma<<<dim3(DMODEL/128, NROWS/128), 256>>>(
            (const float*)py, W_out + (size_t)l*DINNER*DMODEL, nullptr,
            (float*)pm, DMODEL, DINNER);

        k_res_ln<<<NROWS, 256>>>(ln_w, ln_b, l);
    }

    k_linear_out<<<NROWS, 160>>>(lin_out_w, lin_out_b, out);
}

// round 4
// speedup vs baseline: 1.4057x; 1.0881x over previous
#include <cuda_runtime.h>
#include <cuda_bf16.h>
#include <cstdint>
#include <math.h>

// ---------------- config ----------------
#define BATCH   16
#define SEQ     2048
#define NCH     64
#define DMODEL  256
#define DINNER  512
#define DSTATE  64
#define NHEADS  8
#define HP      64
#define CONVDIM 640          // DINNER + 2*DSTATE
#define DPROJ   1160         // 2*DINNER + 2*DSTATE + NHEADS
#define NROWS   (BATCH*SEQ)  // 32768
#define NLAYERS 4
#define LN_EPS  1e-5f
#define DPROJP  1280         // DPROJ padded to 128

// ---------------- scratch (device globals; allocation-free) ----------------
__device__ float g_h[NROWS*DMODEL];      // residual stream (fp32)
__device__ float g_zx[NROWS*DPROJ];      // zxbcdt
__device__ float g_xact[NROWS*CONVDIM];  // silu(conv(xBC)+b)
__device__ float g_dt[NROWS*NHEADS];
__device__ float g_dA[NROWS*NHEADS];
__device__ float g_y[NROWS*DINNER];      // raw scan output
__device__ float g_m[NROWS*DMODEL];      // y @ W_out

// bf16 hi/lo activation copies (GEMM A operands)
__device__ __nv_bfloat16 g_xb[NROWS*NCH],    g_xl[NROWS*NCH];
__device__ __nv_bfloat16 g_hb[NROWS*DMODEL], g_hl[NROWS*DMODEL];
__device__ __nv_bfloat16 g_yb[NROWS*DINNER], g_yl[NROWS*DINNER];

// bf16 hi/lo transposed weights (GEMM B operands), [Npad][K]
__device__ __nv_bfloat16 g_linh[DMODEL*NCH],            g_linl[DMODEL*NCH];
__device__ __nv_bfloat16 g_winh[NLAYERS*DPROJP*DMODEL], g_winl[NLAYERS*DPROJP*DMODEL];
__device__ __nv_bfloat16 g_wouth[NLAYERS*DMODEL*DINNER], g_woutl[NLAYERS*DMODEL*DINNER];

__device__ __forceinline__ float siluf(float x) {
    return x * (1.f / (1.f + __expf(-x)));
}

__device__ __forceinline__ uint32_t smem_u32(const void* p) {
    uint32_t a;
    asm("{ .reg .u64 t; cvta.to.shared.u64 t, %1; cvt.u32.u64 %0, t; }"
        : "=r"(a) : "l"(p));
    return a;
}

#define LDM_X4(r0, r1, r2, r3, addr) \
    asm volatile("ldmatrix.sync.aligned.m8n8.x4.shared.b16 {%0,%1,%2,%3}, [%4];" \
        : "=r"(r0), "=r"(r1), "=r"(r2), "=r"(r3) : "r"(addr))

#define MMA_BF16(c, a, b0v, b1v) \
    asm volatile("mma.sync.aligned.m16n8k16.row.col.f32.bf16.bf16.f32 " \
        "{%0,%1,%2,%3}, {%4,%5,%6,%7}, {%8,%9}, {%0,%1,%2,%3};" \
        : "+f"((c)[0]), "+f"((c)[1]), "+f"((c)[2]), "+f"((c)[3]) \
        : "r"((a)[0]), "r"((a)[1]), "r"((a)[2]), "r"((a)[3]), \
          "r"(b0v), "r"(b1v))

#define CP16(dst, src) \
    asm volatile("cp.async.cg.shared.global [%0], [%1], 16;" \
        :: "r"(dst), "l"(src) : "memory")
#define CPCOMMIT() asm volatile("cp.async.commit_group;" ::: "memory")
#define CPWAIT(n)  asm volatile("cp.async.wait_group %0;" :: "n"(n) : "memory")

// ---------------- weight / input conversion kernels ----------------
// src fp32 [K][N] (row-major, stride N) -> dst hi/lo bf16 [Npad][K]; pads with 0
__global__ void k_cvt_w(const float* __restrict__ src,
                        __nv_bfloat16* __restrict__ dh,
                        __nv_bfloat16* __restrict__ dl,
                        int K, int N, int Npad, int srcStrideLayer, int dstStrideLayer)
{
    int n = blockIdx.x;
    int l = blockIdx.y;
    int k = threadIdx.x;                 // blockDim.x == K
    float v = (n < N) ? src[(size_t)l*srcStrideLayer + (size_t)k*N + n] : 0.f;
    __nv_bfloat16 hi = __float2bfloat16_rn(v);
    __nv_bfloat16 lo = __float2bfloat16_rn(v - __bfloat162float(hi));
    size_t o = (size_t)l*dstStrideLayer + (size_t)n*K + k;
    dh[o] = hi; dl[o] = lo;
}

__global__ void k_cvt_x(const float* __restrict__ src,
                        __nv_bfloat16* __restrict__ dh,
                        __nv_bfloat16* __restrict__ dl)
{
    int i = blockIdx.x * 256 + threadIdx.x;
    float v = src[i];
    __nv_bfloat16 hi = __float2bfloat16_rn(v);
    __nv_bfloat16 lo = __float2bfloat16_rn(v - __bfloat162float(hi));
    dh[i] = hi; dl[i] = lo;
}

// ============================================================================
// Tensor-core split-bf16 GEMM with precomputed hi/lo operands + cp.async.
// C[M,N] = A[M,K] @ B[K,N]^(stored as [Npad][K]) (+bias)
// A@B ~= Ah@Bh + Ah@Bl + Al@Bh (fp32 accumulate).
// CTA 128x128, BK=32, 8 warps (4m x 2n), 2-stage cp.async pipeline.
// Optionally also emits hi/lo bf16 of C (Ch/Cl).
// ============================================================================
#define GSTRIDE 40                 // bf16 elems per smem row (80B, 16B-aligned)
#define TILEB   (128*GSTRIDE*2)    // 10240 B
#define STAGEB  (4*TILEB)          // 40960 B
#define GT_SMEM (2*STAGEB)         // 81920 B

__global__ __launch_bounds__(256) void k_gemm_bf16(
    const __nv_bfloat16* __restrict__ Ah, const __nv_bfloat16* __restrict__ Al,
    const __nv_bfloat16* __restrict__ Bh, const __nv_bfloat16* __restrict__ Bl,
    const float* __restrict__ bias, float* __restrict__ C,
    __nv_bfloat16* __restrict__ Ch, __nv_bfloat16* __restrict__ Cl,
    int N, int K)
{
    extern __shared__ __align__(128) uint8_t dsm[];
    const uint32_t smb = smem_u32(dsm);

    int tid = threadIdx.x;
    int wid = tid >> 5, lane = tid & 31;
    int m0 = blockIdx.y * 128, n0 = blockIdx.x * 128;
    int wm = wid & 3, wn = wid >> 2;

    float acc[2][8][4];
#pragma unroll
    for (int mt = 0; mt < 2; mt++)
#pragma unroll
        for (int nt = 0; nt < 8; nt++)
#pragma unroll
            for (int j = 0; j < 4; j++) acc[mt][nt][j] = 0.f;

    // 4 source tiles per stage: Ah, Al, Bh, Bl
    const __nv_bfloat16* srcs[4] = {
        Ah + (size_t)m0 * K, Al + (size_t)m0 * K,
        Bh + (size_t)n0 * K, Bl + (size_t)n0 * K };

    // per-thread copy tasks: tile rows in [0,128), 4x16B parts per row
    const int row0 = tid >> 2, part = tid & 3;   // rows 0..63 (+64 second it)

    // ldmatrix per-lane byte offsets within a tile
    const uint32_t aoff = (uint32_t)((wm*32 + (lane & 7) + ((lane >> 3) & 1) * 8) * (GSTRIDE*2))
                        + ((lane >> 4) & 1) * 16;
    const uint32_t boff = (uint32_t)((wn*64 + (lane & 7) + ((lane >> 4) & 1) * 8) * (GSTRIDE*2))
                        + ((lane >> 3) & 1) * 16;

    const int NC = K >> 5;

    // ---- prologue: load chunk 0 into stage 0 ----
#pragma unroll
    for (int t = 0; t < 4; t++) {
#pragma unroll
        for (int it = 0; it < 2; it++) {
            int r = row0 + it * 64;
            uint32_t d = smb + t * TILEB + (uint32_t)(r * (GSTRIDE*2) + part * 16);
            CP16(d, srcs[t] + (size_t)r * K + part * 8);
        }
    }
    CPCOMMIT();

    for (int c = 0; c < NC; c++) {
        int s = c & 1;
        if (c + 1 < NC) {
            uint32_t sb2 = smb + ((c + 1) & 1) * STAGEB;
            int kb = (c + 1) * 32;
#pragma unroll
            for (int t = 0; t < 4; t++) {
#pragma unroll
                for (int it = 0; it < 2; it++) {
                    int r = row0 + it * 64;
                    uint32_t d = sb2 + t * TILEB + (uint32_t)(r * (GSTRIDE*2) + part * 16);
                    CP16(d, srcs[t] + (size_t)r * K + kb + part * 8);
                }
            }
            CPCOMMIT();
            CPWAIT(1);
        } else {
            CPWAIT(0);
        }
        __syncthreads();

        uint32_t sbase = smb + s * STAGEB;
#pragma unroll
        for (int pass = 0; pass < 3; pass++) {
            uint32_t abase = sbase + (pass == 2 ? TILEB : 0) + aoff;
            uint32_t bbase = sbase + 2 * TILEB + (pass == 1 ? TILEB : 0) + boff;
#pragma unroll
            for (int ks = 0; ks < 2; ks++) {
                uint32_t ra[2][4];
                LDM_X4(ra[0][0], ra[0][1], ra[0][2], ra[0][3], abase + ks * 32);
                LDM_X4(ra[1][0], ra[1][1], ra[1][2], ra[1][3],
                       abase + ks * 32 + 16 * (GSTRIDE*2));
                uint32_t rb[8][2];
#pragma unroll
                for (int g = 0; g < 4; g++) {
                    LDM_X4(rb[2*g][0], rb[2*g][1], rb[2*g+1][0], rb[2*g+1][1],
                           bbase + ks * 32 + g * 16 * (GSTRIDE*2));
                }
#pragma unroll
                for (int mt = 0; mt < 2; mt++)
#pragma unroll
                    for (int nt = 0; nt < 8; nt++)
                        MMA_BF16(acc[mt][nt], ra[mt], rb[nt][0], rb[nt][1]);
            }
        }
        __syncthreads();
    }

    // ---- epilogue ----
    const int gid = lane >> 2, tig = lane & 3;
#pragma unroll
    for (int mt = 0; mt < 2; mt++) {
#pragma unroll
        for (int nt = 0; nt < 8; nt++) {
            int col = n0 + wn * 64 + nt * 8 + tig * 2;
            if (col < N) {
                int r0 = m0 + wm * 32 + mt * 16 + gid;
                float2 v0 = make_float2(acc[mt][nt][0], acc[mt][nt][1]);
                float2 v1 = make_float2(acc[mt][nt][2], acc[mt][nt][3]);
                if (bias) {
                    float b0 = bias[col], b1 = bias[col + 1];
                    v0.x += b0; v0.y += b1; v1.x += b0; v1.y += b1;
                }
                *(float2*)(C + (size_t)r0 * N + col) = v0;
                *(float2*)(C + (size_t)(r0 + 8) * N + col) = v1;
                if (Ch) {
                    __nv_bfloat16 h00 = __float2bfloat16_rn(v0.x);
                    __nv_bfloat16 h01 = __float2bfloat16_rn(v0.y);
                    __nv_bfloat16 h10 = __float2bfloat16_rn(v1.x);
                    __nv_bfloat16 h11 = __float2bfloat16_rn(v1.y);
                    size_t o0 = (size_t)r0 * N + col, o1 = (size_t)(r0 + 8) * N + col;
                    Ch[o0] = h00; Ch[o0+1] = h01; Ch[o1] = h10; Ch[o1+1] = h11;
                    Cl[o0]   = __float2bfloat16_rn(v0.x - __bfloat162float(h00));
                    Cl[o0+1] = __float2bfloat16_rn(v0.y - __bfloat162float(h01));
                    Cl[o1]   = __float2bfloat16_rn(v1.x - __bfloat162float(h10));
                    Cl[o1+1] = __float2bfloat16_rn(v1.y - __bfloat162float(h11));
                }
            }
        }
    }
}

// ------------- causal depthwise conv(4) + SiLU, plus dt/dA precompute -------------
__global__ __launch_bounds__(CONVDIM) void k_conv_dt(
    const float* __restrict__ conv_w, const float* __restrict__ conv_b,
    const float* __restrict__ dt_bias, const float* __restrict__ A_log,
    int layer)
{
    int t = blockIdx.x;
    int b = blockIdx.y;
    int c = threadIdx.x;
    int rowbase = b*SEQ + t;

    const float* wr = conv_w + (size_t)layer*CONVDIM*4 + c*4;
    float s = conv_b[layer*CONVDIM + c];
    const float* zc = g_zx + (size_t)(b*SEQ)*DPROJ + DINNER + c;
#pragma unroll
    for (int j = 0; j < 4; j++) {
        int tt = t - 3 + j;
        if (tt >= 0) s += zc[(size_t)tt*DPROJ] * wr[j];
    }
    g_xact[(size_t)rowbase*CONVDIM + c] = siluf(s);

    if (c < NHEADS) {
        float draw = g_zx[(size_t)rowbase*DPROJ + DINNER + CONVDIM + c]
                     + dt_bias[layer*NHEADS + c];
        float dtv = (draw > 20.f) ? draw : log1pf(expf(draw));
        float Aneg = -expf(A_log[layer*NHEADS + c]);
        g_dt[rowbase*NHEADS + c] = dtv;
        g_dA[rowbase*NHEADS + c] = expf(dtv * Aneg);
    }
}

// ---------------- sequential selective scan (register prefetch) ----------------
__global__ __launch_bounds__(256) void k_scan(
    const float* __restrict__ Dp, int layer)
{
    int b = blockIdx.x >> 3;
    int h = blockIdx.x & 7;
    int tid = threadIdx.x;
    int p  = tid >> 2;
    int q  = tid & 3;
    int n0 = q * 16;

    float S[16];
#pragma unroll
    for (int j = 0; j < 16; j++) S[j] = 0.f;

    float Dh = Dp[layer*NHEADS + h];
    const float* rowp = g_xact + (size_t)(b*SEQ)*CONVDIM;
    const float* dtp  = g_dt  + (size_t)(b*SEQ)*NHEADS + h;
    const float* dAp  = g_dA  + (size_t)(b*SEQ)*NHEADS + h;
    float* yp = g_y + (size_t)(b*SEQ)*DINNER + h*HP + p;

    float xp  = rowp[h*HP + p];
    float dtv = dtp[0];
    float dAv = dAp[0];
    float Bf[16], Cf[16];
#pragma unroll
    for (int i = 0; i < 4; i++) {
        ((float4*)Bf)[i] = *(const float4*)(rowp + DINNER + n0 + i*4);
        ((float4*)Cf)[i] = *(const float4*)(rowp + DINNER + DSTATE + n0 + i*4);
    }

    for (int t = 0; t < SEQ; t++) {
        float xp2 = 0.f, dt2 = 0.f, dA2 = 0.f;
        float Bn[16], Cn[16];
        if (t + 1 < SEQ) {
            const float* r2 = rowp + (size_t)(t+1)*CONVDIM;
            xp2 = r2[h*HP + p];
            dt2 = dtp[(t+1)*NHEADS];
            dA2 = dAp[(t+1)*NHEADS];
#pragma unroll
            for (int i = 0; i < 4; i++) {
                ((float4*)Bn)[i] = *(const float4*)(r2 + DINNER + n0 + i*4);
                ((float4*)Cn)[i] = *(const float4*)(r2 + DINNER + DSTATE + n0 + i*4);
            }
        }

        float coef = dtv * xp;
        float acc = 0.f;
#pragma unroll
        for (int j = 0; j < 16; j++) {
            S[j] = S[j]*dAv + coef*Bf[j];
            acc += S[j]*Cf[j];
        }
        acc += __shfl_xor_sync(0xffffffffu, acc, 1);
        acc += __shfl_xor_sync(0xffffffffu, acc, 2);
        if (q == 0) yp[(size_t)t*DINNER] = acc + Dh*xp;

        xp = xp2; dtv = dt2; dAv = dA2;
#pragma unroll
        for (int j = 0; j < 16; j++) { Bf[j] = Bn[j]; Cf[j] = Cn[j]; }
    }
}

// ---------------- gated RMSNorm -> hi/lo bf16 ----------------
__global__ __launch_bounds__(256) void k_gate_rms(
    const float* __restrict__ norm_w, int layer)
{
    int row = blockIdx.x;
    int tid = threadIdx.x;
    int lane = tid & 31, wid = tid >> 5;
    __shared__ float red[8];

    const float* zrow = g_zx + (size_t)row*DPROJ;
    const float* yrow = g_y + (size_t)row*DINNER;

    float v0 = yrow[tid]       * siluf(zrow[tid]);
    float v1 = yrow[tid + 256] * siluf(zrow[tid + 256]);
    float s = v0*v0 + v1*v1;
#pragma unroll
    for (int o = 16; o > 0; o >>= 1) s += __shfl_xor_sync(0xffffffffu, s, o);
    if (lane == 0) red[wid] = s;
    __syncthreads();
    if (tid < 32) {
        float v = (lane < 8) ? red[lane] : 0.f;
#pragma unroll
        for (int o = 4; o > 0; o >>= 1) v += __shfl_xor_sync(0xffffffffu, v, o);
        if (lane == 0) red[0] = v;
    }
    __syncthreads();
    float scale = rsqrtf(red[0] * (1.f/DINNER) + LN_EPS);
    float o0 = v0 * scale * norm_w[layer*DINNER + tid];
    float o1 = v1 * scale * norm_w[layer*DINNER + tid + 256];
    size_t base = (size_t)row*DINNER;
    __nv_bfloat16 h0 = __float2bfloat16_rn(o0);
    __nv_bfloat16 h1 = __float2bfloat16_rn(o1);
    g_yb[base + tid]       = h0;
    g_yb[base + tid + 256] = h1;
    g_yl[base + tid]       = __float2bfloat16_rn(o0 - __bfloat162float(h0));
    g_yl[base + tid + 256] = __float2bfloat16_rn(o1 - __bfloat162float(h1));
}

// ---------------- residual + LayerNorm -> fp32 + hi/lo bf16 ----------------
__global__ __launch_bounds__(256) void k_res_ln(
    const float* __restrict__ ln_w, const float* __restrict__ ln_b, int layer)
{
    int row = blockIdx.x;
    int tid = threadIdx.x;
    int lane = tid & 31, wid = tid >> 5;
    __shared__ float red1[8], red2[8];

    float u = g_m[(size_t)row*DMODEL + tid] + g_h[(size_t)row*DMODEL + tid];
    float s1 = u, s2 = u*u;
#pragma unroll
    for (int o = 16; o > 0; o >>= 1) {
        s1 += __shfl_xor_sync(0xffffffffu, s1, o);
        s2 += __shfl_xor_sync(0xffffffffu, s2, o);
    }
    if (lane == 0) { red1[wid] = s1; red2[wid] = s2; }
    __syncthreads();
    if (tid < 32) {
        float a = (lane < 8) ? red1[lane] : 0.f;
        float c = (lane < 8) ? red2[lane] : 0.f;
#pragma unroll
        for (int o = 4; o > 0; o >>= 1) {
            a += __shfl_xor_sync(0xffffffffu, a, o);
            c += __shfl_xor_sync(0xffffffffu, c, o);
        }
        if (lane == 0) { red1[0] = a; red2[0] = c; }
    }
    __syncthreads();
    float mu  = red1[0] * (1.f/DMODEL);
    float var = red2[0] * (1.f/DMODEL) - mu*mu;
    float outv = (u - mu) * rsqrtf(var + LN_EPS) * ln_w[layer*DMODEL + tid]
               + ln_b[layer*DMODEL + tid];
    size_t o = (size_t)row*DMODEL + tid;
    g_h[o] = outv;
    __nv_bfloat16 hi = __float2bfloat16_rn(outv);
    g_hb[o] = hi;
    g_hl[o] = __float2bfloat16_rn(outv - __bfloat162float(hi));
}

// ---------------- linear_out: out = h @ W[256,5] + b ----------------
__global__ __launch_bounds__(160) void k_linear_out(
    const float* __restrict__ w, const float* __restrict__ bias,
    float* __restrict__ out)
{
    int row = blockIdx.x;
    int tid = threadIdx.x;
    int wid = tid >> 5;
    int lane = tid & 31;
    const float* hr = g_h + (size_t)row*DMODEL;
    float acc = 0.f;
#pragma unroll
    for (int k = lane; k < DMODEL; k += 32) acc += hr[k] * w[k*5 + wid];
#pragma unroll
    for (int o = 16; o > 0; o >>= 1) acc += __shfl_xor_sync(0xffffffffu, acc, o);
    if (lane == 0) out[(size_t)row*5 + wid] = acc + bias[wid];
}

// ---------------- launcher ----------------
extern "C" void kernel_launch(void* const* d_in, const int* in_sizes, int n_in,
                              void* d_out, int out_size)
{
    const float* x         = (const float*)d_in[0];
    const float* lin_in_w  = (const float*)d_in[1];
    const float* lin_in_b  = (const float*)d_in[2];
    const float* W_in      = (const float*)d_in[3];
    const float* conv_w    = (const float*)d_in[4];
    const float* conv_b    = (const float*)d_in[5];
    const float* dt_bias   = (const float*)d_in[6];
    const float* A_log     = (const float*)d_in[7];
    const float* Dp        = (const float*)d_in[8];
    const float* norm_w    = (const float*)d_in[9];
    const float* W_out     = (const float*)d_in[10];
    const float* ln_w      = (const float*)d_in[11];
    const float* ln_b      = (const float*)d_in[12];
    const float* lin_out_w = (const float*)d_in[13];
    const float* lin_out_b = (const float*)d_in[14];
    float* out = (float*)d_out;

    void *ph, *pz, *pm;
    cudaGetSymbolAddress(&ph, g_h);
    cudaGetSymbolAddress(&pz, g_zx);
    cudaGetSymbolAddress(&pm, g_m);
    void *pxb, *pxl, *phb, *phl, *pyb, *pyl;
    cudaGetSymbolAddress(&pxb, g_xb);  cudaGetSymbolAddress(&pxl, g_xl);
    cudaGetSymbolAddress(&phb, g_hb);  cudaGetSymbolAddress(&phl, g_hl);
    cudaGetSymbolAddress(&pyb, g_yb);  cudaGetSymbolAddress(&pyl, g_yl);
    void *plh, *pll, *pwih, *pwil, *pwoh, *pwol;
    cudaGetSymbolAddress(&plh, g_linh);  cudaGetSymbolAddress(&pll, g_linl);
    cudaGetSymbolAddress(&pwih, g_winh); cudaGetSymbolAddress(&pwil, g_winl);
    cudaGetSymbolAddress(&pwoh, g_wouth); cudaGetSymbolAddress(&pwol, g_woutl);

    static bool attrset = false;
    if (!attrset) {
        cudaFuncSetAttribute(k_gemm_bf16,
            cudaFuncAttributeMaxDynamicSharedMemorySize, GT_SMEM);
        attrset = true;
    }

    // ---- weight / input conversion (once per launch) ----
    k_cvt_x<<<NROWS*NCH/256, 256>>>(x, (__nv_bfloat16*)pxb, (__nv_bfloat16*)pxl);
    k_cvt_w<<<dim3(DMODEL, 1), NCH>>>(lin_in_w, (__nv_bfloat16*)plh,
        (__nv_bfloat16*)pll, NCH, DMODEL, DMODEL, 0, 0);
    k_cvt_w<<<dim3(DPROJP, NLAYERS), DMODEL>>>(W_in, (__nv_bfloat16*)pwih,
        (__nv_bfloat16*)pwil, DMODEL, DPROJ, DPROJP, DMODEL*DPROJ, DPROJP*DMODEL);
    k_cvt_w<<<dim3(DMODEL, NLAYERS), DINNER>>>(W_out, (__nv_bfloat16*)pwoh,
        (__nv_bfloat16*)pwol, DINNER, DMODEL, DMODEL, DINNER*DMODEL, DMODEL*DINNER);

    // linear_in: h = x @ lin_in_w + b  (emit fp32 + hi/lo bf16)
    k_gemm_bf16<<<dim3(2, NROWS/128), 256, GT_SMEM>>>(
        (const __nv_bfloat16*)pxb, (const __nv_bfloat16*)pxl,
        (const __nv_bfloat16*)plh, (const __nv_bfloat16*)pll,
        lin_in_b, (float*)ph,
        (__nv_bfloat16*)phb, (__nv_bfloat16*)phl, DMODEL, NCH);

    for (int l = 0; l < NLAYERS; l++) {
        k_gemm_bf16<<<dim3(DPROJP/128, NROWS/128), 256, GT_SMEM>>>(
            (const __nv_bfloat16*)phb, (const __nv_bfloat16*)phl,
            (const __nv_bfloat16*)pwih + (size_t)l*DPROJP*DMODEL,
            (const __nv_bfloat16*)pwil + (size_t)l*DPROJP*DMODEL,
            nullptr, (float*)pz, nullptr, nullptr, DPROJ, DMODEL);

        k_conv_dt<<<dim3(SEQ, BATCH), CONVDIM>>>(conv_w, conv_b, dt_bias, A_log, l);

        k_scan<<<BATCH*NHEADS, 256>>>(Dp, l);

        k_gate_rms<<<NROWS, 256>>>(norm_w, l);

        k_gemm_bf16<<<dim3(DMODEL/128, NROWS/128), 256, GT_SMEM>>>(
            (const __nv_bfloat16*)pyb, (const __nv_bfloat16*)pyl,
            (const __nv_bfloat16*)pwoh + (size_t)l*DMODEL*DINNER,
            (const __nv_bfloat16*)pwol + (size_t)l*DMODEL*DINNER,
            nullptr, (float*)pm, nullptr, nullptr, DMODEL, DINNER);

        k_res_ln<<<NROWS, 256>>>(ln_w, ln_b, l);
    }

    k_linear_out<<<NROWS, 160>>>(lin_out_w, lin_out_b, out);
}

// round 5
// speedup vs baseline: 2.6891x; 1.9130x over previous
#include <cuda_runtime.h>
#include <cuda_fp16.h>
#include <cstdint>
#include <math.h>

// ---------------- config ----------------
#define BATCH   16
#define SEQ     2048
#define NCH     64
#define DMODEL  256
#define DINNER  512
#define DSTATE  64
#define NHEADS  8
#define HP      64
#define CONVDIM 640          // DINNER + 2*DSTATE
#define DPROJ   1160         // 2*DINNER + 2*DSTATE + NHEADS
#define NROWS   (BATCH*SEQ)  // 32768
#define NLAYERS 4
#define LN_EPS  1e-5f
#define DPROJP  1280         // DPROJ padded to 128

// ---------------- scratch (device globals; allocation-free) ----------------
__device__ float g_h[NROWS*DMODEL];       // residual stream (fp32)
__device__ float g_zx[NROWS*DPROJ];       // zxbcdt
__device__ float g_xact[NROWS*CONVDIM];   // silu(conv(xBC)+b)
__device__ float2 g_dtA[NROWS*NHEADS];    // (softplus dt, exp(dt*A))
__device__ float g_y0[NROWS*DINNER];      // scan partial (n 0..31)
__device__ float g_y1[NROWS*DINNER];      // scan partial (n 32..63)
__device__ float g_m[NROWS*DMODEL];       // y @ W_out

// fp16 activations (GEMM A operands, single precision copy)
__device__ __half g_xh[NROWS*NCH];
__device__ __half g_hh[NROWS*DMODEL];
__device__ __half g_yh[NROWS*DINNER];

// fp16 hi/lo transposed weights (GEMM B operands), [Npad][K]
__device__ __half g_linh[DMODEL*NCH],             g_linl[DMODEL*NCH];
__device__ __half g_winh[NLAYERS*DPROJP*DMODEL],  g_winl[NLAYERS*DPROJP*DMODEL];
__device__ __half g_wouth[NLAYERS*DMODEL*DINNER], g_woutl[NLAYERS*DMODEL*DINNER];

__device__ __forceinline__ float siluf(float x) {
    return x * (1.f / (1.f + __expf(-x)));
}

__device__ __forceinline__ uint32_t smem_u32(const void* p) {
    uint32_t a;
    asm("{ .reg .u64 t; cvta.to.shared.u64 t, %1; cvt.u32.u64 %0, t; }"
        : "=r"(a) : "l"(p));
    return a;
}

#define LDM_X4(r0, r1, r2, r3, addr) \
    asm volatile("ldmatrix.sync.aligned.m8n8.x4.shared.b16 {%0,%1,%2,%3}, [%4];" \
        : "=r"(r0), "=r"(r1), "=r"(r2), "=r"(r3) : "r"(addr))

#define MMA_FP16(c, a, b0v, b1v) \
    asm volatile("mma.sync.aligned.m16n8k16.row.col.f32.f16.f16.f32 " \
        "{%0,%1,%2,%3}, {%4,%5,%6,%7}, {%8,%9}, {%0,%1,%2,%3};" \
        : "+f"((c)[0]), "+f"((c)[1]), "+f"((c)[2]), "+f"((c)[3]) \
        : "r"((a)[0]), "r"((a)[1]), "r"((a)[2]), "r"((a)[3]), \
          "r"(b0v), "r"(b1v))

#define CP16(dst, src) \
    asm volatile("cp.async.cg.shared.global [%0], [%1], 16;" \
        :: "r"(dst), "l"(src) : "memory")
#define CPCOMMIT() asm volatile("cp.async.commit_group;" ::: "memory")
#define CPWAIT(n)  asm volatile("cp.async.wait_group %0;" :: "n"(n) : "memory")

// ---------------- weight / input conversion kernels ----------------
// src fp32 [K][N] (row-major) -> dst hi/lo fp16 [Npad][K]; pads with 0
__global__ void k_cvt_w(const float* __restrict__ src,
                        __half* __restrict__ dh, __half* __restrict__ dl,
                        int K, int N, int srcStrideLayer, int dstStrideLayer)
{
    int n = blockIdx.x;
    int l = blockIdx.y;
    int k = threadIdx.x;                 // blockDim.x == K
    float v = (n < N) ? src[(size_t)l*srcStrideLayer + (size_t)k*N + n] : 0.f;
    __half hi = __float2half_rn(v);
    __half lo = __float2half_rn(v - __half2float(hi));
    size_t o = (size_t)l*dstStrideLayer + (size_t)n*K + k;
    dh[o] = hi; dl[o] = lo;
}

__global__ void k_cvt_x(const float* __restrict__ src, __half* __restrict__ d)
{
    int i = blockIdx.x * 256 + threadIdx.x;
    d[i] = __float2half_rn(src[i]);
}

// ============================================================================
// fp16 tensor-core GEMM, weights split hi/lo (2 passes):
// C[M,N] = A[M,K] @ (Bh+Bl)[K,N](stored [Npad][K]) (+bias), fp32 accumulate.
// Error ~2^-12 (from fp16 rounding of A only).
// CTA 128x128, BK=32, 8 warps (4m x 2n), 2-stage cp.async pipeline.
// ============================================================================
#define GSTRIDE 40                 // fp16 elems per smem row (80B)
#define TILEB   (128*GSTRIDE*2)    // 10240 B
#define STAGEB  (3*TILEB)          // 30720 B (A, Bh, Bl)
#define GT_SMEM (2*STAGEB)         // 61440 B

__global__ __launch_bounds__(256, 2) void k_gemm_fp16(
    const __half* __restrict__ A,
    const __half* __restrict__ Bh, const __half* __restrict__ Bl,
    const float* __restrict__ bias, float* __restrict__ C,
    __half* __restrict__ Ch, int N, int K)
{
    extern __shared__ __align__(128) uint8_t dsm[];
    const uint32_t smb = smem_u32(dsm);

    int tid = threadIdx.x;
    int wid = tid >> 5, lane = tid & 31;
    int m0 = blockIdx.y * 128, n0 = blockIdx.x * 128;
    int wm = wid & 3, wn = wid >> 2;

    float acc[2][8][4];
#pragma unroll
    for (int mt = 0; mt < 2; mt++)
#pragma unroll
        for (int nt = 0; nt < 8; nt++)
#pragma unroll
            for (int j = 0; j < 4; j++) acc[mt][nt][j] = 0.f;

    const __half* srcs[3] = {
        A + (size_t)m0 * K, Bh + (size_t)n0 * K, Bl + (size_t)n0 * K };

    const int row0 = tid >> 2, part = tid & 3;

    const uint32_t aoff = (uint32_t)((wm*32 + (lane & 7) + ((lane >> 3) & 1) * 8) * (GSTRIDE*2))
                        + ((lane >> 4) & 1) * 16;
    const uint32_t boff = (uint32_t)((wn*64 + (lane & 7) + ((lane >> 4) & 1) * 8) * (GSTRIDE*2))
                        + ((lane >> 3) & 1) * 16;

    const int NC = K >> 5;

    // prologue: chunk 0 -> stage 0
#pragma unroll
    for (int t = 0; t < 3; t++) {
#pragma unroll
        for (int it = 0; it < 2; it++) {
            int r = row0 + it * 64;
            uint32_t d = smb + t * TILEB + (uint32_t)(r * (GSTRIDE*2) + part * 16);
            CP16(d, srcs[t] + (size_t)r * K + part * 8);
        }
    }
    CPCOMMIT();

    for (int c = 0; c < NC; c++) {
        int s = c & 1;
        if (c + 1 < NC) {
            uint32_t sb2 = smb + ((c + 1) & 1) * STAGEB;
            int kb = (c + 1) * 32;
#pragma unroll
            for (int t = 0; t < 3; t++) {
#pragma unroll
                for (int it = 0; it < 2; it++) {
                    int r = row0 + it * 64;
                    uint32_t d = sb2 + t * TILEB + (uint32_t)(r * (GSTRIDE*2) + part * 16);
                    CP16(d, srcs[t] + (size_t)r * K + kb + part * 8);
                }
            }
            CPCOMMIT();
            CPWAIT(1);
        } else {
            CPWAIT(0);
        }
        __syncthreads();

        uint32_t sbase = smb + s * STAGEB;
#pragma unroll
        for (int ks = 0; ks < 2; ks++) {
            uint32_t abase = sbase + aoff + ks * 32;
            uint32_t ra[2][4];
            LDM_X4(ra[0][0], ra[0][1], ra[0][2], ra[0][3], abase);
            LDM_X4(ra[1][0], ra[1][1], ra[1][2], ra[1][3],
                   abase + 16 * (GSTRIDE*2));
            uint32_t rb[8][2];
            // pass 1: Bh
            {
                uint32_t bbase = sbase + TILEB + boff + ks * 32;
#pragma unroll
                for (int g = 0; g < 4; g++)
                    LDM_X4(rb[2*g][0], rb[2*g][1], rb[2*g+1][0], rb[2*g+1][1],
                           bbase + g * 16 * (GSTRIDE*2));
#pragma unroll
                for (int mt = 0; mt < 2; mt++)
#pragma unroll
                    for (int nt = 0; nt < 8; nt++)
                        MMA_FP16(acc[mt][nt], ra[mt], rb[nt][0], rb[nt][1]);
            }
            // pass 2: Bl (reuse rb registers)
            {
                uint32_t bbase = sbase + 2 * TILEB + boff + ks * 32;
#pragma unroll
                for (int g = 0; g < 4; g++)
                    LDM_X4(rb[2*g][0], rb[2*g][1], rb[2*g+1][0], rb[2*g+1][1],
                           bbase + g * 16 * (GSTRIDE*2));
#pragma unroll
                for (int mt = 0; mt < 2; mt++)
#pragma unroll
                    for (int nt = 0; nt < 8; nt++)
                        MMA_FP16(acc[mt][nt], ra[mt], rb[nt][0], rb[nt][1]);
            }
        }
        __syncthreads();
    }

    // ---- epilogue ----
    const int gid = lane >> 2, tig = lane & 3;
#pragma unroll
    for (int mt = 0; mt < 2; mt++) {
#pragma unroll
        for (int nt = 0; nt < 8; nt++) {
            int col = n0 + wn * 64 + nt * 8 + tig * 2;
            if (col < N) {
                int r0 = m0 + wm * 32 + mt * 16 + gid;
                float2 v0 = make_float2(acc[mt][nt][0], acc[mt][nt][1]);
                float2 v1 = make_float2(acc[mt][nt][2], acc[mt][nt][3]);
                if (bias) {
                    float b0 = bias[col], b1 = bias[col + 1];
                    v0.x += b0; v0.y += b1; v1.x += b0; v1.y += b1;
                }
                *(float2*)(C + (size_t)r0 * N + col) = v0;
                *(float2*)(C + (size_t)(r0 + 8) * N + col) = v1;
                if (Ch) {
                    *(__half2*)(Ch + (size_t)r0 * N + col) =
                        __floats2half2_rn(v0.x, v0.y);
                    *(__half2*)(Ch + (size_t)(r0 + 8) * N + col) =
                        __floats2half2_rn(v1.x, v1.y);
                }
            }
        }
    }
}

// ------------- causal depthwise conv(4) + SiLU, plus packed dt/dA -------------
__global__ __launch_bounds__(CONVDIM) void k_conv_dt(
    const float* __restrict__ conv_w, const float* __restrict__ conv_b,
    const float* __restrict__ dt_bias, const float* __restrict__ A_log,
    int layer)
{
    int t = blockIdx.x;
    int b = blockIdx.y;
    int c = threadIdx.x;
    int rowbase = b*SEQ + t;

    const float* wr = conv_w + (size_t)layer*CONVDIM*4 + c*4;
    float s = conv_b[layer*CONVDIM + c];
    const float* zc = g_zx + (size_t)(b*SEQ)*DPROJ + DINNER + c;
#pragma unroll
    for (int j = 0; j < 4; j++) {
        int tt = t - 3 + j;
        if (tt >= 0) s += zc[(size_t)tt*DPROJ] * wr[j];
    }
    g_xact[(size_t)rowbase*CONVDIM + c] = siluf(s);

    if (c < NHEADS) {
        float draw = g_zx[(size_t)rowbase*DPROJ + DINNER + CONVDIM + c]
                     + dt_bias[layer*NHEADS + c];
        float dtv = (draw > 20.f) ? draw : log1pf(expf(draw));
        float Aneg = -expf(A_log[layer*NHEADS + c]);
        g_dtA[rowbase*NHEADS + c] = make_float2(dtv, expf(dtv * Aneg));
    }
}

// ---------------- sequential selective scan ----------------
// grid = 256 (b,h,half), block 256: thread -> (p = tid/4, q = tid%4),
// n-slice = half*32 + q*8 (8 state cols per thread). 4-deep register
// prefetch pipeline, unroll 4 (no buffer-copy). Partials to g_y0/g_y1.
__global__ __launch_bounds__(256) void k_scan(
    const float* __restrict__ Dp, int layer)
{
    int bh = blockIdx.x >> 1, half = blockIdx.x & 1;
    int b = bh >> 3, h = bh & 7;
    int tid = threadIdx.x;
    int p = tid >> 2, q = tid & 3;
    int n0 = half*32 + q*8;

    float S[8];
#pragma unroll
    for (int j = 0; j < 8; j++) S[j] = 0.f;

    float Dh = (half == 0) ? Dp[layer*NHEADS + h] : 0.f;

    const float* rowp = g_xact + (size_t)(b*SEQ)*CONVDIM;
    const float2* dap = g_dtA + (size_t)(b*SEQ)*NHEADS + h;
    float* yp = (half == 0 ? g_y0 : g_y1)
              + (size_t)(b*SEQ)*DINNER + h*HP + p;

    float sx[4]; float2 sda[4];
    float sB[4][8], sC[4][8];
#pragma unroll
    for (int u = 0; u < 4; u++) {
        const float* r = rowp + (size_t)u*CONVDIM;
        sx[u]  = r[h*HP + p];
        sda[u] = dap[u*NHEADS];
        ((float4*)sB[u])[0] = *(const float4*)(r + DINNER + n0);
        ((float4*)sB[u])[1] = *(const float4*)(r + DINNER + n0 + 4);
        ((float4*)sC[u])[0] = *(const float4*)(r + DINNER + DSTATE + n0);
        ((float4*)sC[u])[1] = *(const float4*)(r + DINNER + DSTATE + n0 + 4);
    }

    for (int t = 0; t < SEQ; t += 4) {
#pragma unroll
        for (int u = 0; u < 4; u++) {
            float xv = sx[u];
            float2 da = sda[u];
            float coef = da.x * xv;
            float a0 = 0.f, a1 = 0.f;
#pragma unroll
            for (int j = 0; j < 4; j++) {
                S[j] = S[j]*da.y + coef*sB[u][j];
                a0 += S[j]*sC[u][j];
            }
#pragma unroll
            for (int j = 4; j < 8; j++) {
                S[j] = S[j]*da.y + coef*sB[u][j];
                a1 += S[j]*sC[u][j];
            }
            float acc = a0 + a1;
            acc += __shfl_xor_sync(0xffffffffu, acc, 1);
            acc += __shfl_xor_sync(0xffffffffu, acc, 2);
            if (q == 0) yp[(size_t)(t+u)*DINNER] = acc + Dh*xv;

            // prefetch step t+u+4 into slot u
            int tt = t + u + 4; if (tt > SEQ - 1) tt = SEQ - 1;
            const float* r = rowp + (size_t)tt*CONVDIM;
            sx[u]  = r[h*HP + p];
            sda[u] = dap[tt*NHEADS];
            ((float4*)sB[u])[0] = *(const float4*)(r + DINNER + n0);
            ((float4*)sB[u])[1] = *(const float4*)(r + DINNER + n0 + 4);
            ((float4*)sC[u])[0] = *(const float4*)(r + DINNER + DSTATE + n0);
            ((float4*)sC[u])[1] = *(const float4*)(r + DINNER + DSTATE + n0 + 4);
        }
    }
}

// ---------------- gated RMSNorm: y = rmsnorm((y0+y1) * silu(z)) -> fp16 ----------------
__global__ __launch_bounds__(256) void k_gate_rms(
    const float* __restrict__ norm_w, int layer)
{
    int row = blockIdx.x;
    int tid = threadIdx.x;
    int lane = tid & 31, wid = tid >> 5;
    __shared__ float red[8];

    const float* zrow = g_zx + (size_t)row*DPROJ;
    size_t base = (size_t)row*DINNER;

    float v0 = (g_y0[base + tid]       + g_y1[base + tid])       * siluf(zrow[tid]);
    float v1 = (g_y0[base + tid + 256] + g_y1[base + tid + 256]) * siluf(zrow[tid + 256]);
    float s = v0*v0 + v1*v1;
#pragma unroll
    for (int o = 16; o > 0; o >>= 1) s += __shfl_xor_sync(0xffffffffu, s, o);
    if (lane == 0) red[wid] = s;
    __syncthreads();
    if (tid < 32) {
        float v = (lane < 8) ? red[lane] : 0.f;
#pragma unroll
        for (int o = 4; o > 0; o >>= 1) v += __shfl_xor_sync(0xffffffffu, v, o);
        if (lane == 0) red[0] = v;
    }
    __syncthreads();
    float scale = rsqrtf(red[0] * (1.f/DINNER) + LN_EPS);
    g_yh[base + tid]       = __float2half_rn(v0 * scale * norm_w[layer*DINNER + tid]);
    g_yh[base + tid + 256] = __float2half_rn(v1 * scale * norm_w[layer*DINNER + tid + 256]);
}

// ---------------- residual + LayerNorm: h = LN(m + h) -> fp32 + fp16 ----------------
__global__ __launch_bounds__(256) void k_res_ln(
    const float* __restrict__ ln_w, const float* __restrict__ ln_b, int layer)
{
    int row = blockIdx.x;
    int tid = threadIdx.x;
    int lane = tid & 31, wid = tid >> 5;
    __shared__ float red1[8], red2[8];

    float u = g_m[(size_t)row*DMODEL + tid] + g_h[(size_t)row*DMODEL + tid];
    float s1 = u, s2 = u*u;
#pragma unroll
    for (int o = 16; o > 0; o >>= 1) {
        s1 += __shfl_xor_sync(0xffffffffu, s1, o);
        s2 += __shfl_xor_sync(0xffffffffu, s2, o);
    }
    if (lane == 0) { red1[wid] = s1; red2[wid] = s2; }
    __syncthreads();
    if (tid < 32) {
        float a = (lane < 8) ? red1[lane] : 0.f;
        float c = (lane < 8) ? red2[lane] : 0.f;
#pragma unroll
        for (int o = 4; o > 0; o >>= 1) {
            a += __shfl_xor_sync(0xffffffffu, a, o);
            c += __shfl_xor_sync(0xffffffffu, c, o);
        }
        if (lane == 0) { red1[0] = a; red2[0] = c; }
    }
    __syncthreads();
    float mu  = red1[0] * (1.f/DMODEL);
    float var = red2[0] * (1.f/DMODEL) - mu*mu;
    float outv = (u - mu) * rsqrtf(var + LN_EPS) * ln_w[layer*DMODEL + tid]
               + ln_b[layer*DMODEL + tid];
    size_t o = (size_t)row*DMODEL + tid;
    g_h[o]  = outv;
    g_hh[o] = __float2half_rn(outv);
}

// ---------------- linear_out: out = h @ W[256,5] + b ----------------
__global__ __launch_bounds__(160) void k_linear_out(
    const float* __restrict__ w, const float* __restrict__ bias,
    float* __restrict__ out)
{
    int row = blockIdx.x;
    int tid = threadIdx.x;
    int wid = tid >> 5;
    int lane = tid & 31;
    const float* hr = g_h + (size_t)row*DMODEL;
    float acc = 0.f;
#pragma unroll
    for (int k = lane; k < DMODEL; k += 32) acc += hr[k] * w[k*5 + wid];
#pragma unroll
    for (int o = 16; o > 0; o >>= 1) acc += __shfl_xor_sync(0xffffffffu, acc, o);
    if (lane == 0) out[(size_t)row*5 + wid] = acc + bias[wid];
}

// ---------------- launcher ----------------
extern "C" void kernel_launch(void* const* d_in, const int* in_sizes, int n_in,
                              void* d_out, int out_size)
{
    const float* x         = (const float*)d_in[0];
    const float* lin_in_w  = (const float*)d_in[1];
    const float* lin_in_b  = (const float*)d_in[2];
    const float* W_in      = (const float*)d_in[3];
    const float* conv_w    = (const float*)d_in[4];
    const float* conv_b    = (const float*)d_in[5];
    const float* dt_bias   = (const float*)d_in[6];
    const float* A_log     = (const float*)d_in[7];
    const float* Dp        = (const float*)d_in[8];
    const float* norm_w    = (const float*)d_in[9];
    const float* W_out     = (const float*)d_in[10];
    const float* ln_w      = (const float*)d_in[11];
    const float* ln_b      = (const float*)d_in[12];
    const float* lin_out_w = (const float*)d_in[13];
    const float* lin_out_b = (const float*)d_in[14];
    float* out = (float*)d_out;

    void *ph, *pz, *pm;
    cudaGetSymbolAddress(&ph, g_h);
    cudaGetSymbolAddress(&pz, g_zx);
    cudaGetSymbolAddress(&pm, g_m);
    void *pxh, *phh, *pyh;
    cudaGetSymbolAddress(&pxh, g_xh);
    cudaGetSymbolAddress(&phh, g_hh);
    cudaGetSymbolAddress(&pyh, g_yh);
    void *plh, *pll, *pwih, *pwil, *pwoh, *pwol;
    cudaGetSymbolAddress(&plh, g_linh);   cudaGetSymbolAddress(&pll, g_linl);
    cudaGetSymbolAddress(&pwih, g_winh);  cudaGetSymbolAddress(&pwil, g_winl);
    cudaGetSymbolAddress(&pwoh, g_wouth); cudaGetSymbolAddress(&pwol, g_woutl);

    static bool attrset = false;
    if (!attrset) {
        cudaFuncSetAttribute(k_gemm_fp16,
            cudaFuncAttributeMaxDynamicSharedMemorySize, GT_SMEM);
        attrset = true;
    }

    // ---- conversions ----
    k_cvt_x<<<NROWS*NCH/256, 256>>>(x, (__half*)pxh);
    k_cvt_w<<<dim3(DMODEL, 1), NCH>>>(lin_in_w, (__half*)plh, (__half*)pll,
        NCH, DMODEL, 0, 0);
    k_cvt_w<<<dim3(DPROJP, NLAYERS), DMODEL>>>(W_in, (__half*)pwih, (__half*)pwil,
        DMODEL, DPROJ, DMODEL*DPROJ, DPROJP*DMODEL);
    k_cvt_w<<<dim3(DMODEL, NLAYERS), DINNER>>>(W_out, (__half*)pwoh, (__half*)pwol,
        DINNER, DMODEL, DINNER*DMODEL, DMODEL*DINNER);

    // linear_in: h = x @ lin_in_w + b
    k_gemm_fp16<<<dim3(2, NROWS/128), 256, GT_SMEM>>>(
        (const __half*)pxh, (const __half*)plh, (const __half*)pll,
        lin_in_b, (float*)ph, (__half*)phh, DMODEL, NCH);

    for (int l = 0; l < NLAYERS; l++) {
        k_gemm_fp16<<<dim3(DPROJP/128, NROWS/128), 256, GT_SMEM>>>(
            (const __half*)phh,
            (const __half*)pwih + (size_t)l*DPROJP*DMODEL,
            (const __half*)pwil + (size_t)l*DPROJP*DMODEL,
            nullptr, (float*)pz, nullptr, DPROJ, DMODEL);

        k_conv_dt<<<dim3(SEQ, BATCH), CONVDIM>>>(conv_w, conv_b, dt_bias, A_log, l);

        k_scan<<<256, 256>>>(Dp, l);

        k_gate_rms<<<NROWS, 256>>>(norm_w, l);

        k_gemm_fp16<<<dim3(DMODEL/128, NROWS/128), 256, GT_SMEM>>>(
            (const __half*)pyh,
            (const __half*)pwoh + (size_t)l*DMODEL*DINNER,
            (const __half*)pwol + (size_t)l*DMODEL*DINNER,
            nullptr, (float*)pm, nullptr, DMODEL, DINNER);

        k_res_ln<<<NROWS, 256>>>(ln_w, ln_b, l);
    }

    k_linear_out<<<NROWS, 160>>>(lin_out_w, lin_out_b, out);
}

// round 6
// speedup vs baseline: 2.7977x; 1.0404x over previous
#include <cuda_runtime.h>
#include <cuda_fp16.h>
#include <cstdint>
#include <math.h>

// ---------------- config ----------------
#define BATCH   16
#define SEQ     2048
#define NCH     64
#define DMODEL  256
#define DINNER  512
#define DSTATE  64
#define NHEADS  8
#define HP      64
#define CONVDIM 640          // DINNER + 2*DSTATE
#define DPROJ   1160         // 2*DINNER + 2*DSTATE + NHEADS
#define NROWS   (BATCH*SEQ)  // 32768
#define NLAYERS 4
#define LN_EPS  1e-5f
#define DPROJP  1280         // DPROJ padded to 128

// ---------------- scratch (device globals; allocation-free) ----------------
__device__ float g_h[NROWS*DMODEL];       // residual stream (fp32)
__device__ float g_zx[NROWS*DPROJ];       // zxbcdt
__device__ float g_xact[NROWS*CONVDIM];   // silu(conv(xBC)+b)
__device__ float2 g_dtA[NROWS*NHEADS];    // (softplus dt, exp(dt*A))
__device__ float g_y0[NROWS*DINNER];      // scan partial (n 0..31)
__device__ float g_y1[NROWS*DINNER];      // scan partial (n 32..63)
__device__ float g_m[NROWS*DMODEL];       // y @ W_out

// fp16 activations (GEMM A operands)
__device__ __half g_xh[NROWS*NCH];
__device__ __half g_hh[NROWS*DMODEL];
__device__ __half g_yh[NROWS*DINNER];

// fp16 transposed weights (GEMM B operands), [Npad][K]
__device__ __half g_linw[DMODEL*NCH];
__device__ __half g_winw[NLAYERS*DPROJP*DMODEL];
__device__ __half g_woutw[NLAYERS*DMODEL*DINNER];

__device__ __forceinline__ float siluf(float x) {
    return x * (1.f / (1.f + __expf(-x)));
}

__device__ __forceinline__ uint32_t smem_u32(const void* p) {
    uint32_t a;
    asm("{ .reg .u64 t; cvta.to.shared.u64 t, %1; cvt.u32.u64 %0, t; }"
        : "=r"(a) : "l"(p));
    return a;
}

#define LDM_X4(r0, r1, r2, r3, addr) \
    asm volatile("ldmatrix.sync.aligned.m8n8.x4.shared.b16 {%0,%1,%2,%3}, [%4];" \
        : "=r"(r0), "=r"(r1), "=r"(r2), "=r"(r3) : "r"(addr))

#define MMA_FP16(c, a, b0v, b1v) \
    asm volatile("mma.sync.aligned.m16n8k16.row.col.f32.f16.f16.f32 " \
        "{%0,%1,%2,%3}, {%4,%5,%6,%7}, {%8,%9}, {%0,%1,%2,%3};" \
        : "+f"((c)[0]), "+f"((c)[1]), "+f"((c)[2]), "+f"((c)[3]) \
        : "r"((a)[0]), "r"((a)[1]), "r"((a)[2]), "r"((a)[3]), \
          "r"(b0v), "r"(b1v))

#define CP16(dst, src) \
    asm volatile("cp.async.cg.shared.global [%0], [%1], 16;" \
        :: "r"(dst), "l"(src) : "memory")
#define CPCOMMIT() asm volatile("cp.async.commit_group;" ::: "memory")
#define CPWAIT(n)  asm volatile("cp.async.wait_group %0;" :: "n"(n) : "memory")

// ---------------- weight / input conversion kernels ----------------
// src fp32 [K][N] (row-major) -> dst fp16 [Npad][K]; pads with 0
__global__ void k_cvt_w(const float* __restrict__ src, __half* __restrict__ dh,
                        int K, int N, int srcStrideLayer, int dstStrideLayer)
{
    int n = blockIdx.x;
    int l = blockIdx.y;
    int k = threadIdx.x;                 // blockDim.x == K
    float v = (n < N) ? src[(size_t)l*srcStrideLayer + (size_t)k*N + n] : 0.f;
    dh[(size_t)l*dstStrideLayer + (size_t)n*K + k] = __float2half_rn(v);
}

__global__ void k_cvt_x(const float* __restrict__ src, __half* __restrict__ d)
{
    int i = blockIdx.x * 256 + threadIdx.x;
    d[i] = __float2half_rn(src[i]);
}

// ============================================================================
// Single-pass fp16 tensor-core GEMM:
// C[M,N] = A[M,K] @ B[K,N](stored [Npad][K]) (+bias), fp32 accumulate.
// CTA 128x128, BK=32, 8 warps (4m x 2n), 2-stage cp.async pipeline.
// ============================================================================
#define GSTRIDE 40                 // fp16 elems per smem row (80B)
#define TILEB   (128*GSTRIDE*2)    // 10240 B
#define STAGEB  (2*TILEB)          // 20480 B (A, B)
#define GT_SMEM (2*STAGEB)         // 40960 B

__global__ __launch_bounds__(256, 2) void k_gemm_fp16(
    const __half* __restrict__ A, const __half* __restrict__ B,
    const float* __restrict__ bias, float* __restrict__ C,
    __half* __restrict__ Ch, int N, int K)
{
    extern __shared__ __align__(128) uint8_t dsm[];
    const uint32_t smb = smem_u32(dsm);

    int tid = threadIdx.x;
    int wid = tid >> 5, lane = tid & 31;
    int m0 = blockIdx.y * 128, n0 = blockIdx.x * 128;
    int wm = wid & 3, wn = wid >> 2;

    float acc[2][8][4];
#pragma unroll
    for (int mt = 0; mt < 2; mt++)
#pragma unroll
        for (int nt = 0; nt < 8; nt++)
#pragma unroll
            for (int j = 0; j < 4; j++) acc[mt][nt][j] = 0.f;

    const __half* srcs[2] = { A + (size_t)m0 * K, B + (size_t)n0 * K };

    const int row0 = tid >> 2, part = tid & 3;

    const uint32_t aoff = (uint32_t)((wm*32 + (lane & 7) + ((lane >> 3) & 1) * 8) * (GSTRIDE*2))
                        + ((lane >> 4) & 1) * 16;
    const uint32_t boff = (uint32_t)((wn*64 + (lane & 7) + ((lane >> 4) & 1) * 8) * (GSTRIDE*2))
                        + ((lane >> 3) & 1) * 16;

    const int NC = K >> 5;

    // prologue: chunk 0 -> stage 0
#pragma unroll
    for (int t = 0; t < 2; t++) {
#pragma unroll
        for (int it = 0; it < 2; it++) {
            int r = row0 + it * 64;
            uint32_t d = smb + t * TILEB + (uint32_t)(r * (GSTRIDE*2) + part * 16);
            CP16(d, srcs[t] + (size_t)r * K + part * 8);
        }
    }
    CPCOMMIT();

    for (int c = 0; c < NC; c++) {
        int s = c & 1;
        if (c + 1 < NC) {
            uint32_t sb2 = smb + ((c + 1) & 1) * STAGEB;
            int kb = (c + 1) * 32;
#pragma unroll
            for (int t = 0; t < 2; t++) {
#pragma unroll
                for (int it = 0; it < 2; it++) {
                    int r = row0 + it * 64;
                    uint32_t d = sb2 + t * TILEB + (uint32_t)(r * (GSTRIDE*2) + part * 16);
                    CP16(d, srcs[t] + (size_t)r * K + kb + part * 8);
                }
            }
            CPCOMMIT();
            CPWAIT(1);
        } else {
            CPWAIT(0);
        }
        __syncthreads();

        uint32_t sbase = smb + s * STAGEB;
#pragma unroll
        for (int ks = 0; ks < 2; ks++) {
            uint32_t abase = sbase + aoff + ks * 32;
            uint32_t ra[2][4];
            LDM_X4(ra[0][0], ra[0][1], ra[0][2], ra[0][3], abase);
            LDM_X4(ra[1][0], ra[1][1], ra[1][2], ra[1][3],
                   abase + 16 * (GSTRIDE*2));
            uint32_t rb[8][2];
            uint32_t bbase = sbase + TILEB + boff + ks * 32;
#pragma unroll
            for (int g = 0; g < 4; g++)
                LDM_X4(rb[2*g][0], rb[2*g][1], rb[2*g+1][0], rb[2*g+1][1],
                       bbase + g * 16 * (GSTRIDE*2));
#pragma unroll
            for (int mt = 0; mt < 2; mt++)
#pragma unroll
                for (int nt = 0; nt < 8; nt++)
                    MMA_FP16(acc[mt][nt], ra[mt], rb[nt][0], rb[nt][1]);
        }
        __syncthreads();
    }

    // ---- epilogue ----
    const int gid = lane >> 2, tig = lane & 3;
#pragma unroll
    for (int mt = 0; mt < 2; mt++) {
#pragma unroll
        for (int nt = 0; nt < 8; nt++) {
            int col = n0 + wn * 64 + nt * 8 + tig * 2;
            if (col < N) {
                int r0 = m0 + wm * 32 + mt * 16 + gid;
                float2 v0 = make_float2(acc[mt][nt][0], acc[mt][nt][1]);
                float2 v1 = make_float2(acc[mt][nt][2], acc[mt][nt][3]);
                if (bias) {
                    float b0 = bias[col], b1 = bias[col + 1];
                    v0.x += b0; v0.y += b1; v1.x += b0; v1.y += b1;
                }
                *(float2*)(C + (size_t)r0 * N + col) = v0;
                *(float2*)(C + (size_t)(r0 + 8) * N + col) = v1;
                if (Ch) {
                    *(__half2*)(Ch + (size_t)r0 * N + col) =
                        __floats2half2_rn(v0.x, v0.y);
                    *(__half2*)(Ch + (size_t)(r0 + 8) * N + col) =
                        __floats2half2_rn(v1.x, v1.y);
                }
            }
        }
    }
}

// ------------- causal depthwise conv(4) + SiLU, plus packed dt/dA -------------
__global__ __launch_bounds__(CONVDIM) void k_conv_dt(
    const float* __restrict__ conv_w, const float* __restrict__ conv_b,
    const float* __restrict__ dt_bias, const float* __restrict__ A_log,
    int layer)
{
    int t = blockIdx.x;
    int b = blockIdx.y;
    int c = threadIdx.x;
    int rowbase = b*SEQ + t;

    const float* wr = conv_w + (size_t)layer*CONVDIM*4 + c*4;
    float s = conv_b[layer*CONVDIM + c];
    const float* zc = g_zx + (size_t)(b*SEQ)*DPROJ + DINNER + c;
#pragma unroll
    for (int j = 0; j < 4; j++) {
        int tt = t - 3 + j;
        if (tt >= 0) s += zc[(size_t)tt*DPROJ] * wr[j];
    }
    g_xact[(size_t)rowbase*CONVDIM + c] = siluf(s);

    if (c < NHEADS) {
        float draw = g_zx[(size_t)rowbase*DPROJ + DINNER + CONVDIM + c]
                     + dt_bias[layer*NHEADS + c];
        float dtv = (draw > 20.f) ? draw : log1pf(expf(draw));
        float Aneg = -expf(A_log[layer*NHEADS + c]);
        g_dtA[rowbase*NHEADS + c] = make_float2(dtv, expf(dtv * Aneg));
    }
}

// ---------------- sequential selective scan ----------------
__global__ __launch_bounds__(256) void k_scan(
    const float* __restrict__ Dp, int layer)
{
    int bh = blockIdx.x >> 1, half = blockIdx.x & 1;
    int b = bh >> 3, h = bh & 7;
    int tid = threadIdx.x;
    int p = tid >> 2, q = tid & 3;
    int n0 = half*32 + q*8;

    float S[8];
#pragma unroll
    for (int j = 0; j < 8; j++) S[j] = 0.f;

    float Dh = (half == 0) ? Dp[layer*NHEADS + h] : 0.f;

    const float* rowp = g_xact + (size_t)(b*SEQ)*CONVDIM;
    const float2* dap = g_dtA + (size_t)(b*SEQ)*NHEADS + h;
    float* yp = (half == 0 ? g_y0 : g_y1)
              + (size_t)(b*SEQ)*DINNER + h*HP + p;

    float sx[4]; float2 sda[4];
    float sB[4][8], sC[4][8];
#pragma unroll
    for (int u = 0; u < 4; u++) {
        const float* r = rowp + (size_t)u*CONVDIM;
        sx[u]  = r[h*HP + p];
        sda[u] = dap[u*NHEADS];
        ((float4*)sB[u])[0] = *(const float4*)(r + DINNER + n0);
        ((float4*)sB[u])[1] = *(const float4*)(r + DINNER + n0 + 4);
        ((float4*)sC[u])[0] = *(const float4*)(r + DINNER + DSTATE + n0);
        ((float4*)sC[u])[1] = *(const float4*)(r + DINNER + DSTATE + n0 + 4);
    }

    for (int t = 0; t < SEQ; t += 4) {
#pragma unroll
        for (int u = 0; u < 4; u++) {
            float xv = sx[u];
            float2 da = sda[u];
            float coef = da.x * xv;
            float a0 = 0.f, a1 = 0.f;
#pragma unroll
            for (int j = 0; j < 4; j++) {
                S[j] = S[j]*da.y + coef*sB[u][j];
                a0 += S[j]*sC[u][j];
            }
#pragma unroll
            for (int j = 4; j < 8; j++) {
                S[j] = S[j]*da.y + coef*sB[u][j];
                a1 += S[j]*sC[u][j];
            }
            float acc = a0 + a1;
            acc += __shfl_xor_sync(0xffffffffu, acc, 1);
            acc += __shfl_xor_sync(0xffffffffu, acc, 2);
            if (q == 0) yp[(size_t)(t+u)*DINNER] = acc + Dh*xv;

            int tt = t + u + 4; if (tt > SEQ - 1) tt = SEQ - 1;
            const float* r = rowp + (size_t)tt*CONVDIM;
            sx[u]  = r[h*HP + p];
            sda[u] = dap[tt*NHEADS];
            ((float4*)sB[u])[0] = *(const float4*)(r + DINNER + n0);
            ((float4*)sB[u])[1] = *(const float4*)(r + DINNER + n0 + 4);
            ((float4*)sC[u])[0] = *(const float4*)(r + DINNER + DSTATE + n0);
            ((float4*)sC[u])[1] = *(const float4*)(r + DINNER + DSTATE + n0 + 4);
        }
    }
}

// ---------------- gated RMSNorm: y = rmsnorm((y0+y1) * silu(z)) -> fp16 ----------------
__global__ __launch_bounds__(256) void k_gate_rms(
    const float* __restrict__ norm_w, int layer)
{
    int row = blockIdx.x;
    int tid = threadIdx.x;
    int lane = tid & 31, wid = tid >> 5;
    __shared__ float red[8];

    const float* zrow = g_zx + (size_t)row*DPROJ;
    size_t base = (size_t)row*DINNER;

    float v0 = (g_y0[base + tid]       + g_y1[base + tid])       * siluf(zrow[tid]);
    float v1 = (g_y0[base + tid + 256] + g_y1[base + tid + 256]) * siluf(zrow[tid + 256]);
    float s = v0*v0 + v1*v1;
#pragma unroll
    for (int o = 16; o > 0; o >>= 1) s += __shfl_xor_sync(0xffffffffu, s, o);
    if (lane == 0) red[wid] = s;
    __syncthreads();
    if (tid < 32) {
        float v = (lane < 8) ? red[lane] : 0.f;
#pragma unroll
        for (int o = 4; o > 0; o >>= 1) v += __shfl_xor_sync(0xffffffffu, v, o);
        if (lane == 0) red[0] = v;
    }
    __syncthreads();
    float scale = rsqrtf(red[0] * (1.f/DINNER) + LN_EPS);
    g_yh[base + tid]       = __float2half_rn(v0 * scale * norm_w[layer*DINNER + tid]);
    g_yh[base + tid + 256] = __float2half_rn(v1 * scale * norm_w[layer*DINNER + tid + 256]);
}

// ---------------- residual + LayerNorm: h = LN(m + h) -> fp32 + fp16 ----------------
__global__ __launch_bounds__(256) void k_res_ln(
    const float* __restrict__ ln_w, const float* __restrict__ ln_b, int layer)
{
    int row = blockIdx.x;
    int tid = threadIdx.x;
    int lane = tid & 31, wid = tid >> 5;
    __shared__ float red1[8], red2[8];

    float u = g_m[(size_t)row*DMODEL + tid] + g_h[(size_t)row*DMODEL + tid];
    float s1 = u, s2 = u*u;
#pragma unroll
    for (int o = 16; o > 0; o >>= 1) {
        s1 += __shfl_xor_sync(0xffffffffu, s1, o);
        s2 += __shfl_xor_sync(0xffffffffu, s2, o);
    }
    if (lane == 0) { red1[wid] = s1; red2[wid] = s2; }
    __syncthreads();
    if (tid < 32) {
        float a = (lane < 8) ? red1[lane] : 0.f;
        float c = (lane < 8) ? red2[lane] : 0.f;
#pragma unroll
        for (int o = 4; o > 0; o >>= 1) {
            a += __shfl_xor_sync(0xffffffffu, a, o);
            c += __shfl_xor_sync(0xffffffffu, c, o);
        }
        if (lane == 0) { red1[0] = a; red2[0] = c; }
    }
    __syncthreads();
    float mu  = red1[0] * (1.f/DMODEL);
    float var = red2[0] * (1.f/DMODEL) - mu*mu;
    float outv = (u - mu) * rsqrtf(var + LN_EPS) * ln_w[layer*DMODEL + tid]
               + ln_b[layer*DMODEL + tid];
    size_t o = (size_t)row*DMODEL + tid;
    g_h[o]  = outv;
    g_hh[o] = __float2half_rn(outv);
}

// ---------------- linear_out: out = h @ W[256,5] + b ----------------
__global__ __launch_bounds__(160) void k_linear_out(
    const float* __restrict__ w, const float* __restrict__ bias,
    float* __restrict__ out)
{
    int row = blockIdx.x;
    int tid = threadIdx.x;
    int wid = tid >> 5;
    int lane = tid & 31;
    const float* hr = g_h + (size_t)row*DMODEL;
    float acc = 0.f;
#pragma unroll
    for (int k = lane; k < DMODEL; k += 32) acc += hr[k] * w[k*5 + wid];
#pragma unroll
    for (int o = 16; o > 0; o >>= 1) acc += __shfl_xor_sync(0xffffffffu, acc, o);
    if (lane == 0) out[(size_t)row*5 + wid] = acc + bias[wid];
}

// ---------------- launcher ----------------
extern "C" void kernel_launch(void* const* d_in, const int* in_sizes, int n_in,
                              void* d_out, int out_size)
{
    const float* x         = (const float*)d_in[0];
    const float* lin_in_w  = (const float*)d_in[1];
    const float* lin_in_b  = (const float*)d_in[2];
    const float* W_in      = (const float*)d_in[3];
    const float* conv_w    = (const float*)d_in[4];
    const float* conv_b    = (const float*)d_in[5];
    const float* dt_bias   = (const float*)d_in[6];
    const float* A_log     = (const float*)d_in[7];
    const float* Dp        = (const float*)d_in[8];
    const float* norm_w    = (const float*)d_in[9];
    const float* W_out     = (const float*)d_in[10];
    const float* ln_w      = (const float*)d_in[11];
    const float* ln_b      = (const float*)d_in[12];
    const float* lin_out_w = (const float*)d_in[13];
    const float* lin_out_b = (const float*)d_in[14];
    float* out = (float*)d_out;

    void *ph, *pz, *pm;
    cudaGetSymbolAddress(&ph, g_h);
    cudaGetSymbolAddress(&pz, g_zx);
    cudaGetSymbolAddress(&pm, g_m);
    void *pxh, *phh, *pyh;
    cudaGetSymbolAddress(&pxh, g_xh);
    cudaGetSymbolAddress(&phh, g_hh);
    cudaGetSymbolAddress(&pyh, g_yh);
    void *plw, *pwiw, *pwow;
    cudaGetSymbolAddress(&plw, g_linw);
    cudaGetSymbolAddress(&pwiw, g_winw);
    cudaGetSymbolAddress(&pwow, g_woutw);

    static bool attrset = false;
    if (!attrset) {
        cudaFuncSetAttribute(k_gemm_fp16,
            cudaFuncAttributeMaxDynamicSharedMemorySize, GT_SMEM);
        attrset = true;
    }

    // ---- conversions ----
    k_cvt_x<<<NROWS*NCH/256, 256>>>(x, (__half*)pxh);
    k_cvt_w<<<dim3(DMODEL, 1), NCH>>>(lin_in_w, (__half*)plw, NCH, DMODEL, 0, 0);
    k_cvt_w<<<dim3(DPROJP, NLAYERS), DMODEL>>>(W_in, (__half*)pwiw,
        DMODEL, DPROJ, DMODEL*DPROJ, DPROJP*DMODEL);
    k_cvt_w<<<dim3(DMODEL, NLAYERS), DINNER>>>(W_out, (__half*)pwow,
        DINNER, DMODEL, DINNER*DMODEL, DMODEL*DINNER);

    // linear_in: h = x @ lin_in_w + b
    k_gemm_fp16<<<dim3(2, NROWS/128), 256, GT_SMEM>>>(
        (const __half*)pxh, (const __half*)plw,
        lin_in_b, (float*)ph, (__half*)phh, DMODEL, NCH);

    for (int l = 0; l < NLAYERS; l++) {
        k_gemm_fp16<<<dim3(DPROJP/128, NROWS/128), 256, GT_SMEM>>>(
            (const __half*)phh,
            (const __half*)pwiw + (size_t)l*DPROJP*DMODEL,
            nullptr, (float*)pz, nullptr, DPROJ, DMODEL);

        k_conv_dt<<<dim3(SEQ, BATCH), CONVDIM>>>(conv_w, conv_b, dt_bias, A_log, l);

        k_scan<<<256, 256>>>(Dp, l);

        k_gate_rms<<<NROWS, 256>>>(norm_w, l);

        k_gemm_fp16<<<dim3(DMODEL/128, NROWS/128), 256, GT_SMEM>>>(
            (const __half*)pyh,
            (const __half*)pwow + (size_t)l*DMODEL*DINNER,
            nullptr, (float*)pm, nullptr, DMODEL, DINNER);

        k_res_ln<<<NROWS, 256>>>(ln_w, ln_b, l);
    }

    k_linear_out<<<NROWS, 160>>>(lin_out_w, lin_out_b, out);
}

// round 7
// speedup vs baseline: 3.2058x; 1.1459x over previous
#include <cuda_runtime.h>
#include <cuda_fp16.h>
#include <cstdint>
#include <math.h>

// ---------------- config ----------------
#define BATCH   16
#define SEQ     2048
#define NCH     64
#define DMODEL  256
#define DINNER  512
#define DSTATE  64
#define NHEADS  8
#define HP      64
#define CONVDIM 640          // DINNER + 2*DSTATE
#define DPROJ   1160         // 2*DINNER + 2*DSTATE + NHEADS
#define NROWS   (BATCH*SEQ)  // 32768
#define NLAYERS 4
#define LN_EPS  1e-5f
#define DPROJP  1280         // DPROJ padded to 128
#define TCH     32           // conv time-chunk

// ---------------- scratch (device globals; allocation-free) ----------------
__device__ float  g_h[NROWS*DMODEL];        // residual stream (fp32)
__device__ __half g_hh[NROWS*DMODEL];       // fp16 copy of h
__device__ __half g_zxh[NROWS*DPROJ];       // zxbcdt (fp16)
__device__ __half g_xacth[NROWS*CONVDIM];   // silu(conv(xBC)+b) (fp16)
__device__ float2 g_dtA[NROWS*NHEADS];      // (softplus dt, exp(dt*A)) fp32
__device__ __half g_y0h[NROWS*DINNER];      // scan partial (n 0..31)
__device__ __half g_y1h[NROWS*DINNER];      // scan partial (n 32..63)
__device__ __half g_mh[NROWS*DMODEL];       // y @ W_out (fp16)

// fp16 activations (GEMM A operands)
__device__ __half g_xh[NROWS*NCH];
__device__ __half g_yh[NROWS*DINNER];

// fp16 transposed weights (GEMM B operands), [Npad][K]
__device__ __half g_linw[DMODEL*NCH];
__device__ __half g_winw[NLAYERS*DPROJP*DMODEL];
__device__ __half g_woutw[NLAYERS*DMODEL*DINNER];

__device__ __forceinline__ float siluf(float x) {
    return x * (1.f / (1.f + __expf(-x)));
}

__device__ __forceinline__ uint32_t smem_u32(const void* p) {
    uint32_t a;
    asm("{ .reg .u64 t; cvta.to.shared.u64 t, %1; cvt.u32.u64 %0, t; }"
        : "=r"(a) : "l"(p));
    return a;
}

#define LDM_X4(r0, r1, r2, r3, addr) \
    asm volatile("ldmatrix.sync.aligned.m8n8.x4.shared.b16 {%0,%1,%2,%3}, [%4];" \
        : "=r"(r0), "=r"(r1), "=r"(r2), "=r"(r3) : "r"(addr))

#define MMA_FP16(c, a, b0v, b1v) \
    asm volatile("mma.sync.aligned.m16n8k16.row.col.f32.f16.f16.f32 " \
        "{%0,%1,%2,%3}, {%4,%5,%6,%7}, {%8,%9}, {%0,%1,%2,%3};" \
        : "+f"((c)[0]), "+f"((c)[1]), "+f"((c)[2]), "+f"((c)[3]) \
        : "r"((a)[0]), "r"((a)[1]), "r"((a)[2]), "r"((a)[3]), \
          "r"(b0v), "r"(b1v))

#define CP16(dst, src) \
    asm volatile("cp.async.cg.shared.global [%0], [%1], 16;" \
        :: "r"(dst), "l"(src) : "memory")
#define CPCOMMIT() asm volatile("cp.async.commit_group;" ::: "memory")
#define CPWAIT(n)  asm volatile("cp.async.wait_group %0;" :: "n"(n) : "memory")

// ---------------- weight / input conversion ----------------
__global__ void k_cvt_w(const float* __restrict__ src, __half* __restrict__ dh,
                        int K, int N, int srcStrideLayer, int dstStrideLayer)
{
    int n = blockIdx.x;
    int l = blockIdx.y;
    int k = threadIdx.x;                 // blockDim.x == K
    float v = (n < N) ? src[(size_t)l*srcStrideLayer + (size_t)k*N + n] : 0.f;
    dh[(size_t)l*dstStrideLayer + (size_t)n*K + k] = __float2half_rn(v);
}

__global__ void k_cvt_x(const float* __restrict__ src, __half* __restrict__ d)
{
    int i = blockIdx.x * 256 + threadIdx.x;
    d[i] = __float2half_rn(src[i]);
}

// ============================================================================
// Single-pass fp16 tensor-core GEMM, optional fp32 and/or fp16 outputs.
// C[M,N] = A[M,K] @ B[K,N](stored [Npad][K]) (+bias), fp32 accumulate.
// CTA 128x128, BK=32, 8 warps (4m x 2n), 2-stage cp.async pipeline.
// ============================================================================
#define GSTRIDE 40                 // fp16 elems per smem row (80B)
#define TILEB   (128*GSTRIDE*2)    // 10240 B
#define STAGEB  (2*TILEB)          // 20480 B (A, B)
#define GT_SMEM (2*STAGEB)         // 40960 B

__global__ __launch_bounds__(256, 2) void k_gemm_fp16(
    const __half* __restrict__ A, const __half* __restrict__ B,
    const float* __restrict__ bias, float* __restrict__ C,
    __half* __restrict__ Ch, int N, int K)
{
    extern __shared__ __align__(128) uint8_t dsm[];
    const uint32_t smb = smem_u32(dsm);

    int tid = threadIdx.x;
    int wid = tid >> 5, lane = tid & 31;
    int m0 = blockIdx.y * 128, n0 = blockIdx.x * 128;
    int wm = wid & 3, wn = wid >> 2;

    float acc[2][8][4];
#pragma unroll
    for (int mt = 0; mt < 2; mt++)
#pragma unroll
        for (int nt = 0; nt < 8; nt++)
#pragma unroll
            for (int j = 0; j < 4; j++) acc[mt][nt][j] = 0.f;

    const __half* srcs[2] = { A + (size_t)m0 * K, B + (size_t)n0 * K };
    const int row0 = tid >> 2, part = tid & 3;

    const uint32_t aoff = (uint32_t)((wm*32 + (lane & 7) + ((lane >> 3) & 1) * 8) * (GSTRIDE*2))
                        + ((lane >> 4) & 1) * 16;
    const uint32_t boff = (uint32_t)((wn*64 + (lane & 7) + ((lane >> 4) & 1) * 8) * (GSTRIDE*2))
                        + ((lane >> 3) & 1) * 16;

    const int NC = K >> 5;

#pragma unroll
    for (int t = 0; t < 2; t++) {
#pragma unroll
        for (int it = 0; it < 2; it++) {
            int r = row0 + it * 64;
            uint32_t d = smb + t * TILEB + (uint32_t)(r * (GSTRIDE*2) + part * 16);
            CP16(d, srcs[t] + (size_t)r * K + part * 8);
        }
    }
    CPCOMMIT();

    for (int c = 0; c < NC; c++) {
        int s = c & 1;
        if (c + 1 < NC) {
            uint32_t sb2 = smb + ((c + 1) & 1) * STAGEB;
            int kb = (c + 1) * 32;
#pragma unroll
            for (int t = 0; t < 2; t++) {
#pragma unroll
                for (int it = 0; it < 2; it++) {
                    int r = row0 + it * 64;
                    uint32_t d = sb2 + t * TILEB + (uint32_t)(r * (GSTRIDE*2) + part * 16);
                    CP16(d, srcs[t] + (size_t)r * K + kb + part * 8);
                }
            }
            CPCOMMIT();
            CPWAIT(1);
        } else {
            CPWAIT(0);
        }
        __syncthreads();

        uint32_t sbase = smb + s * STAGEB;
#pragma unroll
        for (int ks = 0; ks < 2; ks++) {
            uint32_t abase = sbase + aoff + ks * 32;
            uint32_t ra[2][4];
            LDM_X4(ra[0][0], ra[0][1], ra[0][2], ra[0][3], abase);
            LDM_X4(ra[1][0], ra[1][1], ra[1][2], ra[1][3],
                   abase + 16 * (GSTRIDE*2));
            uint32_t rb[8][2];
            uint32_t bbase = sbase + TILEB + boff + ks * 32;
#pragma unroll
            for (int g = 0; g < 4; g++)
                LDM_X4(rb[2*g][0], rb[2*g][1], rb[2*g+1][0], rb[2*g+1][1],
                       bbase + g * 16 * (GSTRIDE*2));
#pragma unroll
            for (int mt = 0; mt < 2; mt++)
#pragma unroll
                for (int nt = 0; nt < 8; nt++)
                    MMA_FP16(acc[mt][nt], ra[mt], rb[nt][0], rb[nt][1]);
        }
        __syncthreads();
    }

    // ---- epilogue ----
    const int gid = lane >> 2, tig = lane & 3;
#pragma unroll
    for (int mt = 0; mt < 2; mt++) {
#pragma unroll
        for (int nt = 0; nt < 8; nt++) {
            int col = n0 + wn * 64 + nt * 8 + tig * 2;
            if (col < N) {
                int r0 = m0 + wm * 32 + mt * 16 + gid;
                float2 v0 = make_float2(acc[mt][nt][0], acc[mt][nt][1]);
                float2 v1 = make_float2(acc[mt][nt][2], acc[mt][nt][3]);
                if (bias) {
                    float b0 = bias[col], b1 = bias[col + 1];
                    v0.x += b0; v0.y += b1; v1.x += b0; v1.y += b1;
                }
                if (C) {
                    *(float2*)(C + (size_t)r0 * N + col) = v0;
                    *(float2*)(C + (size_t)(r0 + 8) * N + col) = v1;
                }
                if (Ch) {
                    *(__half2*)(Ch + (size_t)r0 * N + col) =
                        __floats2half2_rn(v0.x, v0.y);
                    *(__half2*)(Ch + (size_t)(r0 + 8) * N + col) =
                        __floats2half2_rn(v1.x, v1.y);
                }
            }
        }
    }
}

// ------------- causal depthwise conv(4) + SiLU + dt/dA, t-chunked -------------
// block = (t-chunk of TCH, batch), 640 threads (one per channel).
// Tap history kept in registers -> ~1.1x read redundancy on fp16 input.
__global__ __launch_bounds__(CONVDIM) void k_conv_dt(
    const float* __restrict__ conv_w, const float* __restrict__ conv_b,
    const float* __restrict__ dt_bias, const float* __restrict__ A_log,
    int layer)
{
    int t0 = blockIdx.x * TCH;
    int b  = blockIdx.y;
    int c  = threadIdx.x;                  // 0..639

    const float* wr = conv_w + (size_t)layer*CONVDIM*4 + c*4;
    float w0 = wr[0], w1 = wr[1], w2 = wr[2], w3 = wr[3];
    float cb = conv_b[layer*CONVDIM + c];

    const __half* zc = g_zxh + (size_t)(b*SEQ)*DPROJ + DINNER + c;
    float h3 = 0.f, h2 = 0.f, h1 = 0.f;
    if (t0 >= 3) {
        h3 = __half2float(zc[(size_t)(t0-3)*DPROJ]);
        h2 = __half2float(zc[(size_t)(t0-2)*DPROJ]);
        h1 = __half2float(zc[(size_t)(t0-1)*DPROJ]);
    }

    float dtb = 0.f, Aneg = 0.f;
    const __half* dz = nullptr;
    if (c < NHEADS) {
        dtb  = dt_bias[layer*NHEADS + c];
        Aneg = -expf(A_log[layer*NHEADS + c]);
        dz   = g_zxh + (size_t)(b*SEQ)*DPROJ + DINNER + CONVDIM + c;
    }

    __half* xo = g_xacth + (size_t)(b*SEQ + t0)*CONVDIM + c;
#pragma unroll 4
    for (int u = 0; u < TCH; u++) {
        float cur = __half2float(zc[(size_t)(t0+u)*DPROJ]);
        float s = cb + h3*w0 + h2*w1 + h1*w2 + cur*w3;
        xo[(size_t)u*CONVDIM] = __float2half_rn(siluf(s));
        h3 = h2; h2 = h1; h1 = cur;
        if (c < NHEADS) {
            float draw = __half2float(dz[(size_t)(t0+u)*DPROJ]) + dtb;
            float dtv = (draw > 20.f) ? draw : log1pf(expf(draw));
            g_dtA[(size_t)(b*SEQ + t0 + u)*NHEADS + c] =
                make_float2(dtv, expf(dtv * Aneg));
        }
    }
}

// ---------------- sequential selective scan (fp16 in/out, fp32 state) ----------------
__global__ __launch_bounds__(256) void k_scan(
    const float* __restrict__ Dp, int layer)
{
    int bh = blockIdx.x >> 1, half = blockIdx.x & 1;
    int b = bh >> 3, h = bh & 7;
    int tid = threadIdx.x;
    int p = tid >> 2, q = tid & 3;
    int n0 = half*32 + q*8;

    float S[8];
#pragma unroll
    for (int j = 0; j < 8; j++) S[j] = 0.f;

    float Dh = (half == 0) ? Dp[layer*NHEADS + h] : 0.f;

    const __half* rowp = g_xacth + (size_t)(b*SEQ)*CONVDIM;
    const float2* dap = g_dtA + (size_t)(b*SEQ)*NHEADS + h;
    __half* yp = (half == 0 ? g_y0h : g_y1h)
               + (size_t)(b*SEQ)*DINNER + h*HP + p;

    float sx[4]; float2 sda[4];
    float sB[4][8], sC[4][8];
#pragma unroll
    for (int u = 0; u < 4; u++) {
        const __half* r = rowp + (size_t)u*CONVDIM;
        sx[u]  = __half2float(r[h*HP + p]);
        sda[u] = dap[u*NHEADS];
        uint4 braw = *(const uint4*)(r + DINNER + n0);
        uint4 craw = *(const uint4*)(r + DINNER + DSTATE + n0);
        const __half2* bhp = (const __half2*)&braw;
        const __half2* chp = (const __half2*)&craw;
#pragma unroll
        for (int j = 0; j < 4; j++) {
            float2 bf = __half22float2(bhp[j]);
            float2 cf = __half22float2(chp[j]);
            sB[u][2*j] = bf.x; sB[u][2*j+1] = bf.y;
            sC[u][2*j] = cf.x; sC[u][2*j+1] = cf.y;
        }
    }

    for (int t = 0; t < SEQ; t += 4) {
#pragma unroll
        for (int u = 0; u < 4; u++) {
            float xv = sx[u];
            float2 da = sda[u];
            float coef = da.x * xv;
            float a0 = 0.f, a1 = 0.f;
#pragma unroll
            for (int j = 0; j < 4; j++) {
                S[j] = S[j]*da.y + coef*sB[u][j];
                a0 += S[j]*sC[u][j];
            }
#pragma unroll
            for (int j = 4; j < 8; j++) {
                S[j] = S[j]*da.y + coef*sB[u][j];
                a1 += S[j]*sC[u][j];
            }
            float acc = a0 + a1;
            acc += __shfl_xor_sync(0xffffffffu, acc, 1);
            acc += __shfl_xor_sync(0xffffffffu, acc, 2);
            if (q == 0) yp[(size_t)(t+u)*DINNER] = __float2half_rn(acc + Dh*xv);

            int tt = t + u + 4; if (tt > SEQ - 1) tt = SEQ - 1;
            const __half* r = rowp + (size_t)tt*CONVDIM;
            sx[u]  = __half2float(r[h*HP + p]);
            sda[u] = dap[tt*NHEADS];
            uint4 braw = *(const uint4*)(r + DINNER + n0);
            uint4 craw = *(const uint4*)(r + DINNER + DSTATE + n0);
            const __half2* bhp = (const __half2*)&braw;
            const __half2* chp = (const __half2*)&craw;
#pragma unroll
            for (int j = 0; j < 4; j++) {
                float2 bf = __half22float2(bhp[j]);
                float2 cf = __half22float2(chp[j]);
                sB[u][2*j] = bf.x; sB[u][2*j+1] = bf.y;
                sC[u][2*j] = cf.x; sC[u][2*j+1] = cf.y;
            }
        }
    }
}

// ---------------- gated RMSNorm: y = rmsnorm((y0+y1) * silu(z)) -> fp16 ----------------
__global__ __launch_bounds__(256) void k_gate_rms(
    const float* __restrict__ norm_w, int layer)
{
    int row = blockIdx.x;
    int tid = threadIdx.x;
    int lane = tid & 31, wid = tid >> 5;
    __shared__ float red[8];

    const __half* zrow = g_zxh + (size_t)row*DPROJ;
    size_t base = (size_t)row*DINNER;

    float y0a = __half2float(g_y0h[base + tid])       + __half2float(g_y1h[base + tid]);
    float y1a = __half2float(g_y0h[base + tid + 256]) + __half2float(g_y1h[base + tid + 256]);
    float v0 = y0a * siluf(__half2float(zrow[tid]));
    float v1 = y1a * siluf(__half2float(zrow[tid + 256]));
    float s = v0*v0 + v1*v1;
#pragma unroll
    for (int o = 16; o > 0; o >>= 1) s += __shfl_xor_sync(0xffffffffu, s, o);
    if (lane == 0) red[wid] = s;
    __syncthreads();
    if (tid < 32) {
        float v = (lane < 8) ? red[lane] : 0.f;
#pragma unroll
        for (int o = 4; o > 0; o >>= 1) v += __shfl_xor_sync(0xffffffffu, v, o);
        if (lane == 0) red[0] = v;
    }
    __syncthreads();
    float scale = rsqrtf(red[0] * (1.f/DINNER) + LN_EPS);
    g_yh[base + tid]       = __float2half_rn(v0 * scale * norm_w[layer*DINNER + tid]);
    g_yh[base + tid + 256] = __float2half_rn(v1 * scale * norm_w[layer*DINNER + tid + 256]);
}

// ---------------- residual + LayerNorm: h = LN(m + h) -> fp32 + fp16 ----------------
__global__ __launch_bounds__(256) void k_res_ln(
    const float* __restrict__ ln_w, const float* __restrict__ ln_b, int layer)
{
    int row = blockIdx.x;
    int tid = threadIdx.x;
    int lane = tid & 31, wid = tid >> 5;
    __shared__ float red1[8], red2[8];

    size_t o = (size_t)row*DMODEL + tid;
    float u = __half2float(g_mh[o]) + g_h[o];
    float s1 = u, s2 = u*u;
#pragma unroll
    for (int ofs = 16; ofs > 0; ofs >>= 1) {
        s1 += __shfl_xor_sync(0xffffffffu, s1, ofs);
        s2 += __shfl_xor_sync(0xffffffffu, s2, ofs);
    }
    if (lane == 0) { red1[wid] = s1; red2[wid] = s2; }
    __syncthreads();
    if (tid < 32) {
        float a = (lane < 8) ? red1[lane] : 0.f;
        float c = (lane < 8) ? red2[lane] : 0.f;
#pragma unroll
        for (int ofs = 4; ofs > 0; ofs >>= 1) {
            a += __shfl_xor_sync(0xffffffffu, a, ofs);
            c += __shfl_xor_sync(0xffffffffu, c, ofs);
        }
        if (lane == 0) { red1[0] = a; red2[0] = c; }
    }
    __syncthreads();
    float mu  = red1[0] * (1.f/DMODEL);
    float var = red2[0] * (1.f/DMODEL) - mu*mu;
    float outv = (u - mu) * rsqrtf(var + LN_EPS) * ln_w[layer*DMODEL + tid]
               + ln_b[layer*DMODEL + tid];
    g_h[o]  = outv;
    g_hh[o] = __float2half_rn(outv);
}

// ---------------- linear_out: out = h @ W[256,5] + b ----------------
__global__ __launch_bounds__(160) void k_linear_out(
    const float* __restrict__ w, const float* __restrict__ bias,
    float* __restrict__ out)
{
    int row = blockIdx.x;
    int tid = threadIdx.x;
    int wid = tid >> 5;
    int lane = tid & 31;
    const float* hr = g_h + (size_t)row*DMODEL;
    float acc = 0.f;
#pragma unroll
    for (int k = lane; k < DMODEL; k += 32) acc += hr[k] * w[k*5 + wid];
#pragma unroll
    for (int o = 16; o > 0; o >>= 1) acc += __shfl_xor_sync(0xffffffffu, acc, o);
    if (lane == 0) out[(size_t)row*5 + wid] = acc + bias[wid];
}

// ---------------- launcher ----------------
extern "C" void kernel_launch(void* const* d_in, const int* in_sizes, int n_in,
                              void* d_out, int out_size)
{
    const float* x         = (const float*)d_in[0];
    const float* lin_in_w  = (const float*)d_in[1];
    const float* lin_in_b  = (const float*)d_in[2];
    const float* W_in      = (const float*)d_in[3];
    const float* conv_w    = (const float*)d_in[4];
    const float* conv_b    = (const float*)d_in[5];
    const float* dt_bias   = (const float*)d_in[6];
    const float* A_log     = (const float*)d_in[7];
    const float* Dp        = (const float*)d_in[8];
    const float* norm_w    = (const float*)d_in[9];
    const float* W_out     = (const float*)d_in[10];
    const float* ln_w      = (const float*)d_in[11];
    const float* ln_b      = (const float*)d_in[12];
    const float* lin_out_w = (const float*)d_in[13];
    const float* lin_out_b = (const float*)d_in[14];
    float* out = (float*)d_out;

    void *ph, *phh, *pzxh, *pmh, *pxh, *pyh;
    cudaGetSymbolAddress(&ph, g_h);
    cudaGetSymbolAddress(&phh, g_hh);
    cudaGetSymbolAddress(&pzxh, g_zxh);
    cudaGetSymbolAddress(&pmh, g_mh);
    cudaGetSymbolAddress(&pxh, g_xh);
    cudaGetSymbolAddress(&pyh, g_yh);
    void *plw, *pwiw, *pwow;
    cudaGetSymbolAddress(&plw, g_linw);
    cudaGetSymbolAddress(&pwiw, g_winw);
    cudaGetSymbolAddress(&pwow, g_woutw);

    static bool attrset = false;
    if (!attrset) {
        cudaFuncSetAttribute(k_gemm_fp16,
            cudaFuncAttributeMaxDynamicSharedMemorySize, GT_SMEM);
        attrset = true;
    }

    // ---- conversions ----
    k_cvt_x<<<NROWS*NCH/256, 256>>>(x, (__half*)pxh);
    k_cvt_w<<<dim3(DMODEL, 1), NCH>>>(lin_in_w, (__half*)plw, NCH, DMODEL, 0, 0);
    k_cvt_w<<<dim3(DPROJP, NLAYERS), DMODEL>>>(W_in, (__half*)pwiw,
        DMODEL, DPROJ, DMODEL*DPROJ, DPROJP*DMODEL);
    k_cvt_w<<<dim3(DMODEL, NLAYERS), DINNER>>>(W_out, (__half*)pwow,
        DINNER, DMODEL, DINNER*DMODEL, DMODEL*DINNER);

    // linear_in: h = x @ lin_in_w + b  (fp32 residual + fp16 copy)
    k_gemm_fp16<<<dim3(2, NROWS/128), 256, GT_SMEM>>>(
        (const __half*)pxh, (const __half*)plw,
        lin_in_b, (float*)ph, (__half*)phh, DMODEL, NCH);

    for (int l = 0; l < NLAYERS; l++) {
        // zxbcdt (fp16 only)
        k_gemm_fp16<<<dim3(DPROJP/128, NROWS/128), 256, GT_SMEM>>>(
            (const __half*)phh,
            (const __half*)pwiw + (size_t)l*DPROJP*DMODEL,
            nullptr, nullptr, (__half*)pzxh, DPROJ, DMODEL);

        k_conv_dt<<<dim3(SEQ/TCH, BATCH), CONVDIM>>>(conv_w, conv_b, dt_bias, A_log, l);

        k_scan<<<256, 256>>>(Dp, l);

        k_gate_rms<<<NROWS, 256>>>(norm_w, l);

        // m = y @ W_out (fp16 only)
        k_gemm_fp16<<<dim3(DMODEL/128, NROWS/128), 256, GT_SMEM>>>(
            (const __half*)pyh,
            (const __half*)pwow + (size_t)l*DMODEL*DINNER,
            nullptr, nullptr, (__half*)pmh, DMODEL, DINNER);

        k_res_ln<<<NROWS, 256>>>(ln_w, ln_b, l);
    }

    k_linear_out<<<NROWS, 160>>>(lin_out_w, lin_out_b, out);
}